// round 1
// baseline (speedup 1.0000x reference)
#include <cuda_runtime.h>
#include <math.h>
#include <stdint.h>

// ===========================================================================
// Performer FastAttention, fp32 SIMT baseline.
// Shapes: q,k,v [2,16,4096,64]; projection [256,64]; out [2,16,4096,64].
// ===========================================================================

namespace fa {

constexpr int B  = 2;
constexpr int H  = 16;
constexpr int N  = 4096;
constexpr int D  = 64;
constexpr int J  = 256;
constexpr int BH = B * H;                       // 32
constexpr size_t NT = (size_t)BH * N;           // 131072 total rows
constexpr int SPLIT = 16;                       // split-K for context GEMM

constexpr float DATA_NORM = 0.35355339059327373f;  // 64^-0.25
constexpr float RATIO     = 0.0625f;               // 256^-0.5
constexpr float DIAG_C    = 0.0625f;               // 0.5 * DATA_NORM^2
constexpr float KEPS      = 1e-4f;

// ---- scratch (device globals; no allocation allowed in kernel_launch) ----
__device__ float    g_qp[NT * J];                          // 134 MB
__device__ float    g_kp[NT * J];                          // 134 MB (logits, then kp)
__device__ unsigned g_kmax_u;                              // ordered-uint float max
__device__ float    g_ctxp[(size_t)BH * SPLIT * J * D];    // 33.5 MB partials
__device__ float    g_ksump[(size_t)BH * SPLIT * J];
__device__ float    g_ctx[(size_t)BH * J * D];
__device__ float    g_ksum[(size_t)BH * J];

// ---- float <-> ordered-uint (for atomicMax over floats incl. negatives) ----
__device__ __forceinline__ unsigned fenc(float f) {
    unsigned u = __float_as_uint(f);
    return (u & 0x80000000u) ? ~u : (u | 0x80000000u);
}
__device__ __forceinline__ float fdec(unsigned u) {
    unsigned b = (u & 0x80000000u) ? (u & 0x7fffffffu) : ~u;
    return __uint_as_float(b);
}

__global__ void k_init() {
    g_kmax_u = 0x007FFFFFu;   // fenc(-inf)
}

// ===========================================================================
// Projection kernel: dd = DATA_NORM * (x @ P^T)  for 64 rows x 256 cols/block.
//   IS_Q: full epilogue -> g_qp = RATIO*(exp(dd - diag - rowmax) + eps)
//  !IS_Q: store (dd - diag) to g_kp; atomicMax global max of dd.
// Dynamic smem: Psm[64][260] (P transposed) + xsm[64][68] (x transposed).
// ===========================================================================
constexpr int P_PAD = 260;   // row stride of Psm (floats), 16B-aligned rows
constexpr int X_PAD = 68;    // row stride of xsm
constexpr size_t SMEM_PROJ = (size_t)(64 * P_PAD + 64 * X_PAD) * sizeof(float);

template <bool IS_Q>
__global__ void __launch_bounds__(256, 2)
k_proj(const float* __restrict__ x, const float* __restrict__ P)
{
    extern __shared__ float sm[];
    float* Psm = sm;                 // [64][P_PAD] indexed Psm[d*P_PAD + j]
    float* xsm = sm + 64 * P_PAD;    // [64][X_PAD] indexed xsm[d*X_PAD + r]
    __shared__ float wm[8];

    const int tid = threadIdx.x;
    const size_t row0 = (size_t)blockIdx.x * 64;

    // stage P transposed: Psm[d][j] = P[j][d]
    for (int i = tid; i < J * D; i += 256) {
        int j = i >> 6, d = i & 63;
        Psm[d * P_PAD + j] = P[i];
    }
    // stage x transposed: xsm[d][r] = x[row0+r][d]
    const float* xb = x + row0 * D;
    for (int i = tid; i < 64 * 64; i += 256) {
        int r = i >> 6, d = i & 63;
        xsm[d * X_PAD + r] = xb[i];
    }
    __syncthreads();

    const int ty = tid >> 4;   // 0..15 -> rows ty*4..ty*4+3
    const int tx = tid & 15;   // 0..15 -> cols tx*16..tx*16+15

    float acc[4][16];
#pragma unroll
    for (int r = 0; r < 4; r++)
#pragma unroll
        for (int c = 0; c < 16; c++) acc[r][c] = 0.f;

#pragma unroll 4
    for (int kk = 0; kk < 64; kk++) {
        float4 a4 = *(const float4*)(xsm + kk * X_PAD + ty * 4);
        float a[4] = {a4.x, a4.y, a4.z, a4.w};
        float b[16];
#pragma unroll
        for (int u = 0; u < 4; u++) {
            float4 b4 = *(const float4*)(Psm + kk * P_PAD + tx * 16 + u * 4);
            b[u * 4 + 0] = b4.x; b[u * 4 + 1] = b4.y;
            b[u * 4 + 2] = b4.z; b[u * 4 + 3] = b4.w;
        }
#pragma unroll
        for (int r = 0; r < 4; r++)
#pragma unroll
            for (int c = 0; c < 16; c++)
                acc[r][c] = fmaf(a[r], b[c], acc[r][c]);
    }

    // diag[r] = DIAG_C * sum_d x[row][d]^2  (each tx sums 4 d's, shfl-reduce over 16)
    float diag[4] = {0.f, 0.f, 0.f, 0.f};
#pragma unroll
    for (int u = 0; u < 4; u++) {
        int d = tx * 4 + u;
#pragma unroll
        for (int r = 0; r < 4; r++) {
            float xv = xsm[d * X_PAD + ty * 4 + r];
            diag[r] = fmaf(xv, xv, diag[r]);
        }
    }
#pragma unroll
    for (int r = 0; r < 4; r++) {
#pragma unroll
        for (int o = 1; o < 16; o <<= 1)
            diag[r] += __shfl_xor_sync(0xffffffffu, diag[r], o);
        diag[r] *= DIAG_C;
    }

    const float NEG_INF = __int_as_float(0xff800000);

    if (IS_Q) {
        // per-row max of dd = DATA_NORM * acc   (DATA_NORM > 0)
#pragma unroll
        for (int r = 0; r < 4; r++) {
            float lm = NEG_INF;
#pragma unroll
            for (int c = 0; c < 16; c++) lm = fmaxf(lm, acc[r][c]);
#pragma unroll
            for (int o = 1; o < 16; o <<= 1)
                lm = fmaxf(lm, __shfl_xor_sync(0xffffffffu, lm, o));
            float m = lm * DATA_NORM;
            float sub = diag[r] + m;
            float* orow = g_qp + (row0 + (size_t)(ty * 4 + r)) * J + tx * 16;
#pragma unroll
            for (int u = 0; u < 4; u++) {
                float4 o4;
                o4.x = RATIO * (__expf(fmaf(acc[r][u*4+0], DATA_NORM, -sub)) + KEPS);
                o4.y = RATIO * (__expf(fmaf(acc[r][u*4+1], DATA_NORM, -sub)) + KEPS);
                o4.z = RATIO * (__expf(fmaf(acc[r][u*4+2], DATA_NORM, -sub)) + KEPS);
                o4.w = RATIO * (__expf(fmaf(acc[r][u*4+3], DATA_NORM, -sub)) + KEPS);
                *(float4*)(orow + u * 4) = o4;
            }
        }
    } else {
        // store logits (dd - diag); reduce block max of dd -> global atomicMax
        float bm = NEG_INF;
#pragma unroll
        for (int r = 0; r < 4; r++) {
            float* orow = g_kp + (row0 + (size_t)(ty * 4 + r)) * J + tx * 16;
#pragma unroll
            for (int u = 0; u < 4; u++) {
                float4 o4;
                o4.x = fmaf(acc[r][u*4+0], DATA_NORM, -diag[r]);
                o4.y = fmaf(acc[r][u*4+1], DATA_NORM, -diag[r]);
                o4.z = fmaf(acc[r][u*4+2], DATA_NORM, -diag[r]);
                o4.w = fmaf(acc[r][u*4+3], DATA_NORM, -diag[r]);
                *(float4*)(orow + u * 4) = o4;
            }
#pragma unroll
            for (int c = 0; c < 16; c++) bm = fmaxf(bm, acc[r][c]);
        }
        bm *= DATA_NORM;
#pragma unroll
        for (int o = 16; o > 0; o >>= 1)
            bm = fmaxf(bm, __shfl_xor_sync(0xffffffffu, bm, o));
        int wid = tid >> 5;
        if ((tid & 31) == 0) wm[wid] = bm;
        __syncthreads();
        if (tid == 0) {
            float m = wm[0];
#pragma unroll
            for (int w = 1; w < 8; w++) m = fmaxf(m, wm[w]);
            atomicMax(&g_kmax_u, fenc(m));
        }
    }
}

// ===========================================================================
// Elementwise exp for kp:  g_kp = RATIO*(exp(logit - global_max) + eps)
// ===========================================================================
__global__ void k_exp()
{
    const float m = fdec(g_kmax_u);
    float4* p = (float4*)g_kp;
    const size_t n4 = NT * J / 4;
    for (size_t i = (size_t)blockIdx.x * blockDim.x + threadIdx.x; i < n4;
         i += (size_t)gridDim.x * blockDim.x) {
        float4 v = p[i];
        v.x = RATIO * (__expf(v.x - m) + KEPS);
        v.y = RATIO * (__expf(v.y - m) + KEPS);
        v.z = RATIO * (__expf(v.z - m) + KEPS);
        v.w = RATIO * (__expf(v.w - m) + KEPS);
        p[i] = v;
    }
}

// ===========================================================================
// Context GEMM (split-K, deterministic partials):
//   ctxp[bh,s][j][e] = sum_{n in split s} kp[bh,n,j] * v[bh,n,e]
//   ksump[bh,s][j]   = sum_{n in split s} kp[bh,n,j]
// grid = (BH, SPLIT), 256 threads. Each thread: 16 j x 4 e accumulators.
// ===========================================================================
__global__ void __launch_bounds__(256, 2)
k_ctx(const float* __restrict__ v)
{
    __shared__ float kpsm[32 * 256];
    __shared__ float vsm[32 * 64];

    const int bh = blockIdx.x;
    const int s  = blockIdx.y;
    const int tid = threadIdx.x;
    const int tj = tid >> 4;    // j-group: rows tj*16..+15 of output
    const int te = tid & 15;    // e-group: cols te*4..+3

    constexpr int NC = N / SPLIT;   // 256 rows per split
    const size_t base = (size_t)bh * N + (size_t)s * NC;
    const float* kpb = g_kp + base * J;
    const float* vb  = v   + base * D;

    float acc[16][4];
#pragma unroll
    for (int jj = 0; jj < 16; jj++)
#pragma unroll
        for (int u = 0; u < 4; u++) acc[jj][u] = 0.f;
    float kss = 0.f;

    for (int r0 = 0; r0 < NC; r0 += 32) {
        __syncthreads();
        for (int i = tid; i < 32 * 256; i += 256) kpsm[i] = kpb[(size_t)r0 * J + i];
        for (int i = tid; i < 32 * 64;  i += 256) vsm[i]  = vb[(size_t)r0 * D + i];
        __syncthreads();

#pragma unroll 4
        for (int r = 0; r < 32; r++) {
            float4 b4 = *(const float4*)(vsm + r * 64 + te * 4);
            float a[16];
#pragma unroll
            for (int u = 0; u < 4; u++) {
                float4 a4 = *(const float4*)(kpsm + r * 256 + tj * 16 + u * 4);
                a[u*4+0] = a4.x; a[u*4+1] = a4.y; a[u*4+2] = a4.z; a[u*4+3] = a4.w;
            }
#pragma unroll
            for (int jj = 0; jj < 16; jj++) {
                acc[jj][0] = fmaf(a[jj], b4.x, acc[jj][0]);
                acc[jj][1] = fmaf(a[jj], b4.y, acc[jj][1]);
                acc[jj][2] = fmaf(a[jj], b4.z, acc[jj][2]);
                acc[jj][3] = fmaf(a[jj], b4.w, acc[jj][3]);
            }
            kss += kpsm[r * 256 + tid];   // column sum, j = tid
        }
    }

    const size_t ob = (size_t)(bh * SPLIT + s);
#pragma unroll
    for (int jj = 0; jj < 16; jj++) {
        float4 o4 = make_float4(acc[jj][0], acc[jj][1], acc[jj][2], acc[jj][3]);
        *(float4*)&g_ctxp[(ob * J + (size_t)(tj * 16 + jj)) * D + te * 4] = o4;
    }
    g_ksump[ob * J + tid] = kss;
}

// Reduce split partials. grid = BH, 256 threads.
__global__ void k_red()
{
    const int bh = blockIdx.x;
    for (int i = threadIdx.x; i < J * D; i += 256) {
        float sum = 0.f;
#pragma unroll
        for (int t = 0; t < SPLIT; t++)
            sum += g_ctxp[(size_t)(bh * SPLIT + t) * J * D + i];
        g_ctx[(size_t)bh * J * D + i] = sum;
    }
    {
        const int j = threadIdx.x;
        float sum = 0.f;
#pragma unroll
        for (int t = 0; t < SPLIT; t++)
            sum += g_ksump[(size_t)(bh * SPLIT + t) * J + j];
        g_ksum[(size_t)bh * J + j] = sum;
    }
}

// ===========================================================================
// Output GEMM: out[row][e] = (1 / (qp[row]·ksum)) * sum_j qp[row][j]*ctx[j][e]
// 64 rows/block; ctx (64KB) + ksum resident in smem; qp staged in 32-col chunks.
// ===========================================================================
constexpr int QP_PAD = 33;
constexpr size_t SMEM_OUT = (size_t)(J * D + J + 64 * QP_PAD) * sizeof(float);

__global__ void __launch_bounds__(256, 2)
k_out(float* __restrict__ out)
{
    extern __shared__ float sm[];
    float* ctxsm  = sm;                 // [256][64]
    float* ksumsm = sm + J * D;         // [256]
    float* qpsm   = ksumsm + J;         // [64][QP_PAD]

    const size_t row0 = (size_t)blockIdx.x * 64;
    const int bh = (int)(row0 / N);
    const int tid = threadIdx.x;
    const int ty = tid >> 4;   // rows ty*4..+3
    const int tx = tid & 15;   // e cols tx*4..+3

    for (int i = tid; i < J * D; i += 256) ctxsm[i] = g_ctx[(size_t)bh * J * D + i];
    ksumsm[tid] = g_ksum[(size_t)bh * J + tid];

    float acc[4][4];
#pragma unroll
    for (int r = 0; r < 4; r++)
#pragma unroll
        for (int u = 0; u < 4; u++) acc[r][u] = 0.f;
    float den[4] = {0.f, 0.f, 0.f, 0.f};

    for (int jc = 0; jc < J; jc += 32) {
        __syncthreads();
        for (int i = tid; i < 64 * 32; i += 256) {
            int r = i >> 5, c = i & 31;
            qpsm[r * QP_PAD + c] = g_qp[(row0 + r) * J + jc + c];
        }
        __syncthreads();

#pragma unroll 8
        for (int jj = 0; jj < 32; jj++) {
            float ksv = ksumsm[jc + jj];
            float4 b4 = *(const float4*)(ctxsm + (jc + jj) * D + tx * 4);
#pragma unroll
            for (int r = 0; r < 4; r++) {
                float a = qpsm[(ty * 4 + r) * QP_PAD + jj];
                acc[r][0] = fmaf(a, b4.x, acc[r][0]);
                acc[r][1] = fmaf(a, b4.y, acc[r][1]);
                acc[r][2] = fmaf(a, b4.z, acc[r][2]);
                acc[r][3] = fmaf(a, b4.w, acc[r][3]);
                den[r]    = fmaf(a, ksv,  den[r]);
            }
        }
    }

#pragma unroll
    for (int r = 0; r < 4; r++) {
        float dinv = 1.f / den[r];
        float4 o4 = make_float4(acc[r][0] * dinv, acc[r][1] * dinv,
                                acc[r][2] * dinv, acc[r][3] * dinv);
        *(float4*)&out[(row0 + (size_t)(ty * 4 + r)) * D + tx * 4] = o4;
    }
}

} // namespace fa

// ===========================================================================
// Launch
// ===========================================================================
extern "C" void kernel_launch(void* const* d_in, const int* in_sizes, int n_in,
                              void* d_out, int out_size)
{
    using namespace fa;
    (void)in_sizes; (void)n_in; (void)out_size;

    const float* q = (const float*)d_in[0];
    const float* k = (const float*)d_in[1];
    const float* v = (const float*)d_in[2];
    const float* P = (const float*)d_in[3];
    float* out = (float*)d_out;

    // Opt-in dynamic smem (idempotent; not a stream op, capture-safe).
    cudaFuncSetAttribute(k_proj<true>,  cudaFuncAttributeMaxDynamicSharedMemorySize, (int)SMEM_PROJ);
    cudaFuncSetAttribute(k_proj<false>, cudaFuncAttributeMaxDynamicSharedMemorySize, (int)SMEM_PROJ);
    cudaFuncSetAttribute(k_out,         cudaFuncAttributeMaxDynamicSharedMemorySize, (int)SMEM_OUT);

    const int nblk = (int)(NT / 64);   // 2048

    k_init<<<1, 1>>>();
    k_proj<false><<<nblk, 256, SMEM_PROJ>>>(k, P);   // k logits + global max
    k_proj<true ><<<nblk, 256, SMEM_PROJ>>>(q, P);   // qp fully formed
    k_exp<<<2048, 256>>>();                          // kp = exp(logit - m)
    k_ctx<<<dim3(BH, SPLIT), 256>>>(v);              // split-K context partials
    k_red<<<BH, 256>>>();                            // reduce partials
    k_out<<<nblk, 256, SMEM_OUT>>>(out);             // qp @ ctx * d_inv
}

// round 2
// speedup vs baseline: 1.8266x; 1.8266x over previous
#include <cuda_runtime.h>
#include <math.h>
#include <stdint.h>

// ===========================================================================
// Performer FastAttention — tensor-pipe (mma.sync tf32, 3x-split) version.
// Shapes: q,k,v [2,16,4096,64]; projection [256,64]; out [2,16,4096,64].
// ===========================================================================

namespace fa {

constexpr int B  = 2;
constexpr int H  = 16;
constexpr int N  = 4096;
constexpr int D  = 64;
constexpr int J  = 256;
constexpr int BH = B * H;                       // 32
constexpr size_t NT = (size_t)BH * N;           // 131072 rows
constexpr int SPLIT = 16;

constexpr float DATA_NORM = 0.35355339059327373f;  // 64^-0.25
constexpr float RATIO     = 0.0625f;               // 256^-0.5
constexpr float DIAG_C    = 0.0625f;               // 0.5 * DATA_NORM^2
constexpr float KEPS      = 1e-4f;

// ---- scratch ----
__device__ float    g_qp[NT * J];                          // 134 MB
__device__ float    g_kp[NT * J];                          // 134 MB (logits)
__device__ unsigned g_kmax_u;
__device__ float    g_ctxp[(size_t)BH * SPLIT * J * D];
__device__ float    g_ksump[(size_t)BH * SPLIT * J];
__device__ float    g_ctx[(size_t)BH * J * D];
__device__ float    g_ksum[(size_t)BH * J];

__device__ __forceinline__ unsigned fenc(float f) {
    unsigned u = __float_as_uint(f);
    return (u & 0x80000000u) ? ~u : (u | 0x80000000u);
}
__device__ __forceinline__ float fdec(unsigned u) {
    unsigned b = (u & 0x80000000u) ? (u & 0x7fffffffu) : ~u;
    return __uint_as_float(b);
}

__global__ void k_init() { g_kmax_u = 0x007FFFFFu; }  // fenc(-inf)

// ---- tf32 split: x ~= hi + lo, both representable in tf32 ----
__device__ __forceinline__ void tf32_split(float x, uint32_t& hi, uint32_t& lo) {
    uint32_t u = __float_as_uint(x);
    hi = u & 0xffffe000u;
    lo = __float_as_uint(x - __uint_as_float(hi));
}

// ---- m16n8k8 tf32 mma ----
__device__ __forceinline__ void mma8(float* c, const uint32_t* a, const uint32_t* b) {
    asm volatile(
        "mma.sync.aligned.m16n8k8.row.col.f32.tf32.tf32.f32 "
        "{%0,%1,%2,%3}, {%4,%5,%6,%7}, {%8,%9}, {%0,%1,%2,%3};"
        : "+f"(c[0]), "+f"(c[1]), "+f"(c[2]), "+f"(c[3])
        : "r"(a[0]), "r"(a[1]), "r"(a[2]), "r"(a[3]), "r"(b[0]), "r"(b[1]));
}

// ===========================================================================
// Projection: dd = DATA_NORM * (X @ P^T); 64 rows x 256 cols per block.
//   IS_Q: g_qp = RATIO*(exp(dd - diag - rowmax)+eps)
//  !IS_Q: g_kp = dd - diag (logits); atomicMax of global max(dd)
// 8 warps as 2(m) x 4(n); warp tile 32x64; K=64 (8 ksteps).
// smem: Psm [256][68] row-major(j,d), xsm [64][68].
// ===========================================================================
constexpr size_t SMEM_PROJ = (size_t)(J * 68 + 64 * 68) * sizeof(float);

template <bool IS_Q>
__global__ void __launch_bounds__(256)
k_proj_t(const float* __restrict__ x, const float* __restrict__ P)
{
    extern __shared__ float sm[];
    float* Psm = sm;                // [256][68]  Psm[j*68+d]
    float* xsm = sm + J * 68;       // [64][68]   xsm[m*68+k]
    __shared__ float diag[64];
    __shared__ float red[64][4];

    const int tid = threadIdx.x;
    const size_t row0 = (size_t)blockIdx.x * 64;

    for (int i = tid; i < J * D; i += 256)
        Psm[(i >> 6) * 68 + (i & 63)] = P[i];
    const float* xb = x + row0 * D;
    for (int i = tid; i < 64 * 64; i += 256)
        xsm[(i >> 6) * 68 + (i & 63)] = xb[i];
    __syncthreads();

    if (tid < 64) {
        float s = 0.f;
#pragma unroll
        for (int kk = 0; kk < 64; kk++) {
            float xv = xsm[tid * 68 + kk];
            s = fmaf(xv, xv, s);
        }
        diag[tid] = s * DIAG_C;
    }

    const int lane = tid & 31, wid = tid >> 5;
    const int wm = wid >> 2, wn = wid & 3;    // warp tile: rows wm*32, cols wn*64
    const int qr = lane >> 2, qc = lane & 3;

    float c[2][8][4];
#pragma unroll
    for (int mt = 0; mt < 2; mt++)
#pragma unroll
        for (int nt = 0; nt < 8; nt++)
#pragma unroll
            for (int u = 0; u < 4; u++) c[mt][nt][u] = 0.f;

#pragma unroll 1
    for (int ks = 0; ks < 8; ks++) {
        const int k0 = ks * 8;
        uint32_t ahi[2][4], alo[2][4];
#pragma unroll
        for (int mt = 0; mt < 2; mt++) {
            int m = wm * 32 + mt * 16 + qr;
            tf32_split(xsm[m * 68 + k0 + qc],           ahi[mt][0], alo[mt][0]);
            tf32_split(xsm[(m + 8) * 68 + k0 + qc],     ahi[mt][1], alo[mt][1]);
            tf32_split(xsm[m * 68 + k0 + 4 + qc],       ahi[mt][2], alo[mt][2]);
            tf32_split(xsm[(m + 8) * 68 + k0 + 4 + qc], ahi[mt][3], alo[mt][3]);
        }
#pragma unroll
        for (int nt = 0; nt < 8; nt++) {
            int j = wn * 64 + nt * 8 + qr;
            uint32_t bhi[2], blo[2];
            tf32_split(Psm[j * 68 + k0 + qc],     bhi[0], blo[0]);
            tf32_split(Psm[j * 68 + k0 + 4 + qc], bhi[1], blo[1]);
#pragma unroll
            for (int mt = 0; mt < 2; mt++) {
                mma8(c[mt][nt], ahi[mt], bhi);
                mma8(c[mt][nt], alo[mt], bhi);
                mma8(c[mt][nt], ahi[mt], blo);
            }
        }
    }

    const float NEG_INF = __int_as_float(0xff800000);

    if (IS_Q) {
        float rmax[2][2];
#pragma unroll
        for (int mt = 0; mt < 2; mt++) { rmax[mt][0] = NEG_INF; rmax[mt][1] = NEG_INF; }
#pragma unroll
        for (int mt = 0; mt < 2; mt++)
#pragma unroll
            for (int nt = 0; nt < 8; nt++) {
                rmax[mt][0] = fmaxf(rmax[mt][0], fmaxf(c[mt][nt][0], c[mt][nt][1]));
                rmax[mt][1] = fmaxf(rmax[mt][1], fmaxf(c[mt][nt][2], c[mt][nt][3]));
            }
#pragma unroll
        for (int mt = 0; mt < 2; mt++)
#pragma unroll
            for (int h = 0; h < 2; h++) {
                rmax[mt][h] = fmaxf(rmax[mt][h], __shfl_xor_sync(0xffffffffu, rmax[mt][h], 1));
                rmax[mt][h] = fmaxf(rmax[mt][h], __shfl_xor_sync(0xffffffffu, rmax[mt][h], 2));
            }
        if (qc == 0) {
#pragma unroll
            for (int mt = 0; mt < 2; mt++) {
                red[wm * 32 + mt * 16 + qr][wn]     = rmax[mt][0];
                red[wm * 32 + mt * 16 + qr + 8][wn] = rmax[mt][1];
            }
        }
        __syncthreads();
        float sub[2][2];
#pragma unroll
        for (int mt = 0; mt < 2; mt++)
#pragma unroll
            for (int h = 0; h < 2; h++) {
                int row = wm * 32 + mt * 16 + qr + h * 8;
                float m4 = fmaxf(fmaxf(red[row][0], red[row][1]),
                                 fmaxf(red[row][2], red[row][3])) * DATA_NORM;
                sub[mt][h] = diag[row] + m4;
            }
#pragma unroll
        for (int mt = 0; mt < 2; mt++)
#pragma unroll
            for (int nt = 0; nt < 8; nt++) {
                int row = wm * 32 + mt * 16 + qr;
                int j = wn * 64 + nt * 8 + qc * 2;
                float2 v0, v1;
                v0.x = RATIO * (__expf(fmaf(c[mt][nt][0], DATA_NORM, -sub[mt][0])) + KEPS);
                v0.y = RATIO * (__expf(fmaf(c[mt][nt][1], DATA_NORM, -sub[mt][0])) + KEPS);
                v1.x = RATIO * (__expf(fmaf(c[mt][nt][2], DATA_NORM, -sub[mt][1])) + KEPS);
                v1.y = RATIO * (__expf(fmaf(c[mt][nt][3], DATA_NORM, -sub[mt][1])) + KEPS);
                *(float2*)&g_qp[(row0 + row) * J + j]       = v0;
                *(float2*)&g_qp[(row0 + row + 8) * J + j]   = v1;
            }
    } else {
        float bm = NEG_INF;
#pragma unroll
        for (int mt = 0; mt < 2; mt++)
#pragma unroll
            for (int nt = 0; nt < 8; nt++)
#pragma unroll
                for (int u = 0; u < 4; u++) bm = fmaxf(bm, c[mt][nt][u]);
#pragma unroll
        for (int o = 16; o > 0; o >>= 1)
            bm = fmaxf(bm, __shfl_xor_sync(0xffffffffu, bm, o));
        if (lane == 0) red[wid][0] = bm;
        __syncthreads();
        if (tid == 0) {
            float m = red[0][0];
#pragma unroll
            for (int w = 1; w < 8; w++) m = fmaxf(m, red[w][0]);
            atomicMax(&g_kmax_u, fenc(m * DATA_NORM));
        }
#pragma unroll
        for (int mt = 0; mt < 2; mt++) {
            int rbase = wm * 32 + mt * 16 + qr;
            float d0 = diag[rbase], d1 = diag[rbase + 8];
#pragma unroll
            for (int nt = 0; nt < 8; nt++) {
                int j = wn * 64 + nt * 8 + qc * 2;
                float2 v0, v1;
                v0.x = fmaf(c[mt][nt][0], DATA_NORM, -d0);
                v0.y = fmaf(c[mt][nt][1], DATA_NORM, -d0);
                v1.x = fmaf(c[mt][nt][2], DATA_NORM, -d1);
                v1.y = fmaf(c[mt][nt][3], DATA_NORM, -d1);
                *(float2*)&g_kp[(row0 + rbase) * J + j]     = v0;
                *(float2*)&g_kp[(row0 + rbase + 8) * J + j] = v1;
            }
        }
    }
}

// ===========================================================================
// Context GEMM (split-K): ctxp[j][e] = sum_n kp[n][j]*v[n][e], ksump[j].
// exp transform fused into kp staging (g_kp holds logits).
// grid (BH, SPLIT); block tile M=256(j) x N=64(e), K-chunk 32.
// 8 warps as 4(m) x 2(n); warp tile 64x32.
// smem: kps [32][264], vs [32][72].
// ===========================================================================
constexpr size_t SMEM_CTX = (size_t)(32 * 264 + 32 * 72) * sizeof(float);

__global__ void __launch_bounds__(256)
k_ctx_t(const float* __restrict__ v)
{
    extern __shared__ float sm[];
    float* kps = sm;              // [32][264]  kps[n*264 + j]
    float* vs  = sm + 32 * 264;   // [32][72]   vs[n*72 + e]

    const int bh = blockIdx.x, s = blockIdx.y;
    const int tid = threadIdx.x, lane = tid & 31, wid = tid >> 5;
    const int wm = wid >> 1, wn = wid & 1;
    const int qr = lane >> 2, qc = lane & 3;
    const float gmax = fdec(g_kmax_u);

    constexpr int NC = N / SPLIT;
    const size_t base = (size_t)bh * N + (size_t)s * NC;

    float c[4][4][4];
#pragma unroll
    for (int mt = 0; mt < 4; mt++)
#pragma unroll
        for (int nt = 0; nt < 4; nt++)
#pragma unroll
            for (int u = 0; u < 4; u++) c[mt][nt][u] = 0.f;
    float kss = 0.f;

    for (int n0 = 0; n0 < NC; n0 += 32) {
        __syncthreads();
        const float* kpr = g_kp + (base + n0) * J + tid;
#pragma unroll
        for (int n = 0; n < 32; n++) {
            float val = RATIO * (__expf(kpr[(size_t)n * J] - gmax) + KEPS);
            kps[n * 264 + tid] = val;
            kss += val;
        }
        for (int i = tid; i < 32 * 64; i += 256)
            vs[(i >> 6) * 72 + (i & 63)] = v[(base + n0 + (i >> 6)) * D + (i & 63)];
        __syncthreads();

#pragma unroll
        for (int kc = 0; kc < 4; kc++) {
            const int k0 = kc * 8;
            uint32_t ahi[4][4], alo[4][4];
#pragma unroll
            for (int mt = 0; mt < 4; mt++) {
                int m = wm * 64 + mt * 16 + qr;
                tf32_split(kps[(k0 + qc) * 264 + m],         ahi[mt][0], alo[mt][0]);
                tf32_split(kps[(k0 + qc) * 264 + m + 8],     ahi[mt][1], alo[mt][1]);
                tf32_split(kps[(k0 + 4 + qc) * 264 + m],     ahi[mt][2], alo[mt][2]);
                tf32_split(kps[(k0 + 4 + qc) * 264 + m + 8], ahi[mt][3], alo[mt][3]);
            }
#pragma unroll
            for (int nt = 0; nt < 4; nt++) {
                int nn = wn * 32 + nt * 8 + qr;
                uint32_t bhi[2], blo[2];
                tf32_split(vs[(k0 + qc) * 72 + nn],     bhi[0], blo[0]);
                tf32_split(vs[(k0 + 4 + qc) * 72 + nn], bhi[1], blo[1]);
#pragma unroll
                for (int mt = 0; mt < 4; mt++) {
                    mma8(c[mt][nt], ahi[mt], bhi);
                    mma8(c[mt][nt], alo[mt], bhi);
                    mma8(c[mt][nt], ahi[mt], blo);
                }
            }
        }
    }

    const size_t ob = (size_t)(bh * SPLIT + s);
#pragma unroll
    for (int mt = 0; mt < 4; mt++)
#pragma unroll
        for (int nt = 0; nt < 4; nt++) {
            int jrow = wm * 64 + mt * 16 + qr;
            int e = wn * 32 + nt * 8 + qc * 2;
            float2 v0 = make_float2(c[mt][nt][0], c[mt][nt][1]);
            float2 v1 = make_float2(c[mt][nt][2], c[mt][nt][3]);
            *(float2*)&g_ctxp[(ob * J + jrow) * D + e]     = v0;
            *(float2*)&g_ctxp[(ob * J + jrow + 8) * D + e] = v1;
        }
    g_ksump[ob * J + tid] = kss;
}

// Reduce split partials. grid = BH, 256 threads.
__global__ void k_red()
{
    const int bh = blockIdx.x;
    for (int i = threadIdx.x; i < J * D; i += 256) {
        float sum = 0.f;
#pragma unroll
        for (int t = 0; t < SPLIT; t++)
            sum += g_ctxp[(size_t)(bh * SPLIT + t) * J * D + i];
        g_ctx[(size_t)bh * J * D + i] = sum;
    }
    {
        const int j = threadIdx.x;
        float sum = 0.f;
#pragma unroll
        for (int t = 0; t < SPLIT; t++)
            sum += g_ksump[(size_t)(bh * SPLIT + t) * J + j];
        g_ksum[(size_t)bh * J + j] = sum;
    }
}

// ===========================================================================
// Output GEMM: out[row][e] = (qp[row] @ ctx)[e] / (qp[row] . ksum)
// Denominator folded in as B-column 64 (cols 65..71 zero).
// Block: M=128 rows, N=72, K=256; 8 warps wm=wid, warp tile 16 x 72.
// smem: qps [128][68], cs [64][76].
// ===========================================================================
constexpr size_t SMEM_OUT = (size_t)(128 * 68 + 64 * 76) * sizeof(float);

__global__ void __launch_bounds__(256)
k_out_t(float* __restrict__ out)
{
    extern __shared__ float sm[];
    float* qps = sm;              // [128][68]
    float* cs  = sm + 128 * 68;   // [64][76]

    const size_t row0 = (size_t)blockIdx.x * 128;
    const int bh = (int)(row0 / N);
    const int tid = threadIdx.x, lane = tid & 31, wid = tid >> 5;
    const int qr = lane >> 2, qc = lane & 3;

    float c[9][4];
#pragma unroll
    for (int nt = 0; nt < 9; nt++)
#pragma unroll
        for (int u = 0; u < 4; u++) c[nt][u] = 0.f;

    for (int jc = 0; jc < J; jc += 64) {
        __syncthreads();
        for (int i = tid; i < 128 * 64; i += 256)
            qps[(i >> 6) * 68 + (i & 63)] = g_qp[(row0 + (i >> 6)) * J + jc + (i & 63)];
        for (int i = tid; i < 64 * 64; i += 256)
            cs[(i >> 6) * 76 + (i & 63)] =
                g_ctx[(size_t)bh * J * D + (size_t)(jc + (i >> 6)) * D + (i & 63)];
        if (tid < 64) {
            cs[tid * 76 + 64] = g_ksum[(size_t)bh * J + jc + tid];
#pragma unroll
            for (int u = 1; u < 8; u++) cs[tid * 76 + 64 + u] = 0.f;
        }
        __syncthreads();

#pragma unroll
        for (int kc = 0; kc < 8; kc++) {
            const int k0 = kc * 8;
            uint32_t ahi[4], alo[4];
            int m = wid * 16 + qr;
            tf32_split(qps[m * 68 + k0 + qc],           ahi[0], alo[0]);
            tf32_split(qps[(m + 8) * 68 + k0 + qc],     ahi[1], alo[1]);
            tf32_split(qps[m * 68 + k0 + 4 + qc],       ahi[2], alo[2]);
            tf32_split(qps[(m + 8) * 68 + k0 + 4 + qc], ahi[3], alo[3]);
#pragma unroll
            for (int nt = 0; nt < 9; nt++) {
                int nn = nt * 8 + qr;
                uint32_t bhi[2], blo[2];
                tf32_split(cs[(k0 + qc) * 76 + nn],     bhi[0], blo[0]);
                tf32_split(cs[(k0 + 4 + qc) * 76 + nn], bhi[1], blo[1]);
                mma8(c[nt], ahi, bhi);
                mma8(c[nt], alo, bhi);
                mma8(c[nt], ahi, blo);
            }
        }
    }

    // denominator sits in column 64 => ntile 8, col offset 0 (qc==0 lanes)
    const int srcl = lane & ~3;
    float den0 = __shfl_sync(0xffffffffu, c[8][0], srcl);
    float den1 = __shfl_sync(0xffffffffu, c[8][2], srcl);
    float di0 = 1.f / den0, di1 = 1.f / den1;

    const int row = wid * 16 + qr;
#pragma unroll
    for (int nt = 0; nt < 8; nt++) {
        int e = nt * 8 + qc * 2;
        float2 v0 = make_float2(c[nt][0] * di0, c[nt][1] * di0);
        float2 v1 = make_float2(c[nt][2] * di1, c[nt][3] * di1);
        *(float2*)&out[(row0 + row) * D + e]     = v0;
        *(float2*)&out[(row0 + row + 8) * D + e] = v1;
    }
}

} // namespace fa

// ===========================================================================
// Launch
// ===========================================================================
extern "C" void kernel_launch(void* const* d_in, const int* in_sizes, int n_in,
                              void* d_out, int out_size)
{
    using namespace fa;
    (void)in_sizes; (void)n_in; (void)out_size;

    const float* q = (const float*)d_in[0];
    const float* k = (const float*)d_in[1];
    const float* v = (const float*)d_in[2];
    const float* P = (const float*)d_in[3];
    float* out = (float*)d_out;

    cudaFuncSetAttribute(k_proj_t<true>,  cudaFuncAttributeMaxDynamicSharedMemorySize, (int)SMEM_PROJ);
    cudaFuncSetAttribute(k_proj_t<false>, cudaFuncAttributeMaxDynamicSharedMemorySize, (int)SMEM_PROJ);
    cudaFuncSetAttribute(k_ctx_t,         cudaFuncAttributeMaxDynamicSharedMemorySize, (int)SMEM_CTX);
    cudaFuncSetAttribute(k_out_t,         cudaFuncAttributeMaxDynamicSharedMemorySize, (int)SMEM_OUT);

    k_init<<<1, 1>>>();
    k_proj_t<false><<<(int)(NT / 64), 256, SMEM_PROJ>>>(k, P);  // k logits + global max
    k_proj_t<true ><<<(int)(NT / 64), 256, SMEM_PROJ>>>(q, P);  // qp fully formed
    k_ctx_t<<<dim3(BH, SPLIT), 256, SMEM_CTX>>>(v);             // fused exp + context partials
    k_red<<<BH, 256>>>();                                       // reduce partials
    k_out_t<<<(int)(NT / 128), 256, SMEM_OUT>>>(out);           // qp @ [ctx|ksum] * 1/den
}

// round 3
// speedup vs baseline: 2.4489x; 1.3407x over previous
#include <cuda_runtime.h>
#include <cuda_bf16.h>
#include <math.h>
#include <stdint.h>

// ===========================================================================
// Performer FastAttention — bf16 3-MMA split (m16n8k16), presplit smem.
// Shapes: q,k,v [2,16,4096,64]; projection [256,64]; out [2,16,4096,64].
// ===========================================================================

namespace fa {

constexpr int B  = 2;
constexpr int H  = 16;
constexpr int N  = 4096;
constexpr int D  = 64;
constexpr int J  = 256;
constexpr int BH = B * H;
constexpr size_t NT = (size_t)BH * N;     // 131072 rows
constexpr int SPLIT = 16;

constexpr float DATA_NORM = 0.35355339059327373f;  // 64^-0.25
constexpr float RATIO     = 0.0625f;               // 256^-0.5
constexpr float DIAG_C    = 0.0625f;               // 0.5 * DATA_NORM^2
constexpr float KEPS      = 1e-4f;

// ---- scratch ----
__device__ float    g_qp[NT * J];
__device__ float    g_kp[NT * J];          // logits
__device__ unsigned g_kmax_u;
__device__ float    g_ctxp[(size_t)BH * SPLIT * J * D];
__device__ float    g_ksump[(size_t)BH * SPLIT * J];
__device__ float    g_ctx[(size_t)BH * J * D];
__device__ float    g_ksum[(size_t)BH * J];
__device__ uint32_t g_Ph[J * 32];          // P hi, bf16x2 packed [j][d/2]
__device__ uint32_t g_Pl[J * 32];          // P lo

__device__ __forceinline__ unsigned fenc(float f) {
    unsigned u = __float_as_uint(f);
    return (u & 0x80000000u) ? ~u : (u | 0x80000000u);
}
__device__ __forceinline__ float fdec(unsigned u) {
    unsigned b = (u & 0x80000000u) ? (u & 0x7fffffffu) : ~u;
    return __uint_as_float(b);
}

// pack two floats as bf16x2 (lo half = a, hi half = b), round-to-nearest
__device__ __forceinline__ uint32_t bpack(float a, float b) {
    uint32_t r;
    asm("cvt.rn.bf16x2.f32 %0, %1, %2;" : "=r"(r) : "f"(b), "f"(a));
    return r;
}
// split pair (a,b) into bf16 hi + bf16 lo packed words
__device__ __forceinline__ void split2(float a, float b, uint32_t& hi, uint32_t& lo) {
    hi = bpack(a, b);
    float ha = __uint_as_float(hi << 16);
    float hb = __uint_as_float(hi & 0xffff0000u);
    lo = bpack(a - ha, b - hb);
}

// m16n8k16 bf16 mma, fp32 accumulate
__device__ __forceinline__ void mma16(float* c, const uint32_t* a, const uint32_t* b) {
    asm volatile(
        "mma.sync.aligned.m16n8k16.row.col.f32.bf16.bf16.f32 "
        "{%0,%1,%2,%3}, {%4,%5,%6,%7}, {%8,%9}, {%0,%1,%2,%3};"
        : "+f"(c[0]), "+f"(c[1]), "+f"(c[2]), "+f"(c[3])
        : "r"(a[0]), "r"(a[1]), "r"(a[2]), "r"(a[3]), "r"(b[0]), "r"(b[1]));
}

// ===========================================================================
// Prep: split projection P [256][64] into g_Ph/g_Pl; init global max cell.
// ===========================================================================
__global__ void k_prep(const float* __restrict__ P)
{
    int i = blockIdx.x * blockDim.x + threadIdx.x;   // 8192 pair slots
    if (i == 0) g_kmax_u = 0x007FFFFFu;              // fenc(-inf)
    if (i < J * 32) {
        int j = i >> 5, c = i & 31;
        uint32_t hi, lo;
        split2(P[j * 64 + 2 * c], P[j * 64 + 2 * c + 1], hi, lo);
        g_Ph[i] = hi;
        g_Pl[i] = lo;
    }
}

// ===========================================================================
// Projection: dd = DATA_NORM * (X @ P^T); 64 rows x 256 cols per block.
//   IS_Q: g_qp = RATIO*(exp(dd - diag - rowmax)+eps)
//  !IS_Q: g_kp = dd - diag (logits); atomicMax global max(dd)
// 8 warps as 2(m) x 4(n); warp tile 32x64; K=64 (4 ksteps of 16).
// smem (u32 units): Phs[256][36], Pls[256][36], xhs[64][36], xls[64][36].
// ===========================================================================
constexpr int KP = 36;   // u32 row stride (K=64 -> 32 u32 + 4 pad)
constexpr size_t SMEM_PROJ = (size_t)(2 * J * KP + 2 * 64 * KP) * sizeof(uint32_t);

template <bool IS_Q>
__global__ void __launch_bounds__(256)
k_proj_t(const float* __restrict__ x)
{
    extern __shared__ uint32_t smu[];
    uint32_t* Phs = smu;                  // [256][36]
    uint32_t* Pls = Phs + J * KP;
    uint32_t* xhs = Pls + J * KP;         // [64][36]
    uint32_t* xls = xhs + 64 * KP;
    __shared__ float diag[64];
    __shared__ float red[64][4];

    const int tid = threadIdx.x;
    const size_t row0 = (size_t)blockIdx.x * 64;
    const float* xb = x + row0 * D;

    // stage pre-split P (u32 copies)
    for (int i = tid; i < J * 32; i += 256) {
        int j = i >> 5, c = i & 31;
        Phs[j * KP + c] = g_Ph[i];
        Pls[j * KP + c] = g_Pl[i];
    }
    // stage + split x
    for (int i = tid; i < 64 * 32; i += 256) {
        int r = i >> 5, c = i & 31;
        float2 f = *(const float2*)(xb + r * 64 + 2 * c);
        uint32_t hi, lo;
        split2(f.x, f.y, hi, lo);
        xhs[r * KP + c] = hi;
        xls[r * KP + c] = lo;
    }
    // diag from global (full fp32 precision)
    if (tid < 64) {
        const float4* xr = (const float4*)(xb + tid * 64);
        float s = 0.f;
#pragma unroll
        for (int i = 0; i < 16; i++) {
            float4 f = xr[i];
            s = fmaf(f.x, f.x, s); s = fmaf(f.y, f.y, s);
            s = fmaf(f.z, f.z, s); s = fmaf(f.w, f.w, s);
        }
        diag[tid] = s * DIAG_C;
    }
    __syncthreads();

    const int lane = tid & 31, wid = tid >> 5;
    const int wm = wid >> 2, wn = wid & 3;   // rows wm*32, cols wn*64
    const int qr = lane >> 2, qc = lane & 3;

    float c[2][8][4];
#pragma unroll
    for (int mt = 0; mt < 2; mt++)
#pragma unroll
        for (int nt = 0; nt < 8; nt++)
#pragma unroll
            for (int u = 0; u < 4; u++) c[mt][nt][u] = 0.f;

#pragma unroll
    for (int ks = 0; ks < 4; ks++) {
        const int kx = ks * 8;
        uint32_t ahi[2][4], alo[2][4];
#pragma unroll
        for (int mt = 0; mt < 2; mt++) {
            int m = wm * 32 + mt * 16 + qr;
            ahi[mt][0] = xhs[m * KP + kx + qc];
            ahi[mt][1] = xhs[(m + 8) * KP + kx + qc];
            ahi[mt][2] = xhs[m * KP + kx + 4 + qc];
            ahi[mt][3] = xhs[(m + 8) * KP + kx + 4 + qc];
            alo[mt][0] = xls[m * KP + kx + qc];
            alo[mt][1] = xls[(m + 8) * KP + kx + qc];
            alo[mt][2] = xls[m * KP + kx + 4 + qc];
            alo[mt][3] = xls[(m + 8) * KP + kx + 4 + qc];
        }
#pragma unroll
        for (int nt = 0; nt < 8; nt++) {
            int j = wn * 64 + nt * 8 + qr;
            uint32_t bhi[2], blo[2];
            bhi[0] = Phs[j * KP + kx + qc];
            bhi[1] = Phs[j * KP + kx + 4 + qc];
            blo[0] = Pls[j * KP + kx + qc];
            blo[1] = Pls[j * KP + kx + 4 + qc];
#pragma unroll
            for (int mt = 0; mt < 2; mt++) {
                mma16(c[mt][nt], ahi[mt], bhi);
                mma16(c[mt][nt], alo[mt], bhi);
                mma16(c[mt][nt], ahi[mt], blo);
            }
        }
    }

    const float NEG_INF = __int_as_float(0xff800000);

    if (IS_Q) {
        float rmax[2][2];
#pragma unroll
        for (int mt = 0; mt < 2; mt++) { rmax[mt][0] = NEG_INF; rmax[mt][1] = NEG_INF; }
#pragma unroll
        for (int mt = 0; mt < 2; mt++)
#pragma unroll
            for (int nt = 0; nt < 8; nt++) {
                rmax[mt][0] = fmaxf(rmax[mt][0], fmaxf(c[mt][nt][0], c[mt][nt][1]));
                rmax[mt][1] = fmaxf(rmax[mt][1], fmaxf(c[mt][nt][2], c[mt][nt][3]));
            }
#pragma unroll
        for (int mt = 0; mt < 2; mt++)
#pragma unroll
            for (int h = 0; h < 2; h++) {
                rmax[mt][h] = fmaxf(rmax[mt][h], __shfl_xor_sync(0xffffffffu, rmax[mt][h], 1));
                rmax[mt][h] = fmaxf(rmax[mt][h], __shfl_xor_sync(0xffffffffu, rmax[mt][h], 2));
            }
        if (qc == 0) {
#pragma unroll
            for (int mt = 0; mt < 2; mt++) {
                red[wm * 32 + mt * 16 + qr][wn]     = rmax[mt][0];
                red[wm * 32 + mt * 16 + qr + 8][wn] = rmax[mt][1];
            }
        }
        __syncthreads();
        float sub[2][2];
#pragma unroll
        for (int mt = 0; mt < 2; mt++)
#pragma unroll
            for (int h = 0; h < 2; h++) {
                int row = wm * 32 + mt * 16 + qr + h * 8;
                float m4 = fmaxf(fmaxf(red[row][0], red[row][1]),
                                 fmaxf(red[row][2], red[row][3])) * DATA_NORM;
                sub[mt][h] = diag[row] + m4;
            }
#pragma unroll
        for (int mt = 0; mt < 2; mt++)
#pragma unroll
            for (int nt = 0; nt < 8; nt++) {
                int row = wm * 32 + mt * 16 + qr;
                int j = wn * 64 + nt * 8 + qc * 2;
                float2 v0, v1;
                v0.x = RATIO * (__expf(fmaf(c[mt][nt][0], DATA_NORM, -sub[mt][0])) + KEPS);
                v0.y = RATIO * (__expf(fmaf(c[mt][nt][1], DATA_NORM, -sub[mt][0])) + KEPS);
                v1.x = RATIO * (__expf(fmaf(c[mt][nt][2], DATA_NORM, -sub[mt][1])) + KEPS);
                v1.y = RATIO * (__expf(fmaf(c[mt][nt][3], DATA_NORM, -sub[mt][1])) + KEPS);
                *(float2*)&g_qp[(row0 + row) * J + j]     = v0;
                *(float2*)&g_qp[(row0 + row + 8) * J + j] = v1;
            }
    } else {
        float bm = NEG_INF;
#pragma unroll
        for (int mt = 0; mt < 2; mt++)
#pragma unroll
            for (int nt = 0; nt < 8; nt++)
#pragma unroll
                for (int u = 0; u < 4; u++) bm = fmaxf(bm, c[mt][nt][u]);
#pragma unroll
        for (int o = 16; o > 0; o >>= 1)
            bm = fmaxf(bm, __shfl_xor_sync(0xffffffffu, bm, o));
        if (lane == 0) red[wid][0] = bm;
        __syncthreads();
        if (tid == 0) {
            float m = red[0][0];
#pragma unroll
            for (int w = 1; w < 8; w++) m = fmaxf(m, red[w][0]);
            atomicMax(&g_kmax_u, fenc(m * DATA_NORM));
        }
#pragma unroll
        for (int mt = 0; mt < 2; mt++) {
            int rbase = wm * 32 + mt * 16 + qr;
            float d0 = diag[rbase], d1 = diag[rbase + 8];
#pragma unroll
            for (int nt = 0; nt < 8; nt++) {
                int j = wn * 64 + nt * 8 + qc * 2;
                float2 v0, v1;
                v0.x = fmaf(c[mt][nt][0], DATA_NORM, -d0);
                v0.y = fmaf(c[mt][nt][1], DATA_NORM, -d0);
                v1.x = fmaf(c[mt][nt][2], DATA_NORM, -d1);
                v1.y = fmaf(c[mt][nt][3], DATA_NORM, -d1);
                *(float2*)&g_kp[(row0 + rbase) * J + j]     = v0;
                *(float2*)&g_kp[(row0 + rbase + 8) * J + j] = v1;
            }
        }
    }
}

// ===========================================================================
// Context GEMM (split-K): ctxp[j][e] = sum_n kp[n][j]*v[n][e]; ksump[j].
// exp fused at staging. grid (BH, SPLIT); 256 thr; 8 warps = 4(m) x 2(n).
// smem (u32): Ah/Al [256][20] (A = kp^T, K=n chunk 32), Bh/Bl [64][20].
// ===========================================================================
constexpr int KC = 20;   // u32 stride for K=32 (16 u32 + 4 pad)
constexpr size_t SMEM_CTX = (size_t)(2 * J * KC + 2 * 64 * KC) * sizeof(uint32_t);

__global__ void __launch_bounds__(256)
k_ctx_t(const float* __restrict__ vg)
{
    extern __shared__ uint32_t smu[];
    uint32_t* Ah = smu;                 // [256][20]
    uint32_t* Al = Ah + J * KC;
    uint32_t* Bh = Al + J * KC;         // [64][20]
    uint32_t* Bl = Bh + 64 * KC;

    const int bh = blockIdx.x, s = blockIdx.y;
    const int tid = threadIdx.x, lane = tid & 31, wid = tid >> 5;
    const int wm = wid >> 1, wn = wid & 1;
    const int qr = lane >> 2, qc = lane & 3;
    const float gmax = fdec(g_kmax_u);

    constexpr int NC = N / SPLIT;       // 256
    const size_t base = (size_t)bh * N + (size_t)s * NC;

    float c[4][4][4];
#pragma unroll
    for (int mt = 0; mt < 4; mt++)
#pragma unroll
        for (int nt = 0; nt < 4; nt++)
#pragma unroll
            for (int u = 0; u < 4; u++) c[mt][nt][u] = 0.f;
    float kss = 0.f;

    const int ve = tid & 63, vh = tid >> 6;    // v staging coords

    for (int n0 = 0; n0 < NC; n0 += 32) {
        __syncthreads();
        // kp: thread = column j; apply exp; split into A (j-major, k=n)
        {
            const float* kpc = g_kp + (base + n0) * J + tid;
#pragma unroll
            for (int n = 0; n < 32; n += 2) {
                float v0 = RATIO * (__expf(kpc[(size_t)n * J] - gmax) + KEPS);
                float v1 = RATIO * (__expf(kpc[(size_t)(n + 1) * J] - gmax) + KEPS);
                kss += v0 + v1;
                uint32_t hi, lo;
                split2(v0, v1, hi, lo);
                Ah[tid * KC + (n >> 1)] = hi;
                Al[tid * KC + (n >> 1)] = lo;
            }
        }
        // v: B[e][k=n]
        {
            const float* vb = vg + (base + n0 + vh * 8) * D + ve;
#pragma unroll
            for (int i = 0; i < 8; i += 2) {
                float f0 = vb[(size_t)i * D];
                float f1 = vb[(size_t)(i + 1) * D];
                uint32_t hi, lo;
                split2(f0, f1, hi, lo);
                Bh[ve * KC + vh * 4 + (i >> 1)] = hi;
                Bl[ve * KC + vh * 4 + (i >> 1)] = lo;
            }
        }
        __syncthreads();

#pragma unroll
        for (int ks = 0; ks < 2; ks++) {
            const int kx = ks * 8;
            uint32_t ahi[4][4], alo[4][4];
#pragma unroll
            for (int mt = 0; mt < 4; mt++) {
                int m = wm * 64 + mt * 16 + qr;
                ahi[mt][0] = Ah[m * KC + kx + qc];
                ahi[mt][1] = Ah[(m + 8) * KC + kx + qc];
                ahi[mt][2] = Ah[m * KC + kx + 4 + qc];
                ahi[mt][3] = Ah[(m + 8) * KC + kx + 4 + qc];
                alo[mt][0] = Al[m * KC + kx + qc];
                alo[mt][1] = Al[(m + 8) * KC + kx + qc];
                alo[mt][2] = Al[m * KC + kx + 4 + qc];
                alo[mt][3] = Al[(m + 8) * KC + kx + 4 + qc];
            }
#pragma unroll
            for (int nt = 0; nt < 4; nt++) {
                int e = wn * 32 + nt * 8 + qr;
                uint32_t bhi[2], blo[2];
                bhi[0] = Bh[e * KC + kx + qc];
                bhi[1] = Bh[e * KC + kx + 4 + qc];
                blo[0] = Bl[e * KC + kx + qc];
                blo[1] = Bl[e * KC + kx + 4 + qc];
#pragma unroll
                for (int mt = 0; mt < 4; mt++) {
                    mma16(c[mt][nt], ahi[mt], bhi);
                    mma16(c[mt][nt], alo[mt], bhi);
                    mma16(c[mt][nt], ahi[mt], blo);
                }
            }
        }
    }

    const size_t ob = (size_t)(bh * SPLIT + s);
#pragma unroll
    for (int mt = 0; mt < 4; mt++)
#pragma unroll
        for (int nt = 0; nt < 4; nt++) {
            int jrow = wm * 64 + mt * 16 + qr;
            int e = wn * 32 + nt * 8 + qc * 2;
            *(float2*)&g_ctxp[(ob * J + jrow) * D + e] =
                make_float2(c[mt][nt][0], c[mt][nt][1]);
            *(float2*)&g_ctxp[(ob * J + jrow + 8) * D + e] =
                make_float2(c[mt][nt][2], c[mt][nt][3]);
        }
    g_ksump[ob * J + tid] = kss;
}

// Reduce split partials. grid = BH, 256 threads.
__global__ void k_red()
{
    const int bh = blockIdx.x;
    for (int i = threadIdx.x; i < J * D; i += 256) {
        float sum = 0.f;
#pragma unroll
        for (int t = 0; t < SPLIT; t++)
            sum += g_ctxp[(size_t)(bh * SPLIT + t) * J * D + i];
        g_ctx[(size_t)bh * J * D + i] = sum;
    }
    {
        const int j = threadIdx.x;
        float sum = 0.f;
#pragma unroll
        for (int t = 0; t < SPLIT; t++)
            sum += g_ksump[(size_t)(bh * SPLIT + t) * J + j];
        g_ksum[(size_t)bh * J + j] = sum;
    }
}

// ===========================================================================
// Output GEMM: out[row][e] = (qp[row] @ ctx)[e] / (qp[row] . ksum)
// den folded as B-row e=64 (rows 65..71 zero). Block 128 rows x 72 x K=256
// (chunks of 64). 8 warps, warp tile 16 x 72.
// smem (u32): Qh/Ql [128][36], Ch/Cl [72][36].
// ===========================================================================
constexpr int KO = 36;
constexpr size_t SMEM_OUT = (size_t)(2 * 128 * KO + 2 * 72 * KO) * sizeof(uint32_t);

__global__ void __launch_bounds__(256)
k_out_t(float* __restrict__ out)
{
    extern __shared__ uint32_t smu[];
    uint32_t* Qh = smu;                  // [128][36]
    uint32_t* Ql = Qh + 128 * KO;
    uint32_t* Ch = Ql + 128 * KO;        // [72][36]
    uint32_t* Cl = Ch + 72 * KO;

    const size_t row0 = (size_t)blockIdx.x * 128;
    const int bh = (int)(row0 / N);
    const size_t cb = (size_t)bh * J * D;
    const int tid = threadIdx.x, lane = tid & 31, wid = tid >> 5;
    const int qr = lane >> 2, qc = lane & 3;

    // zero pad rows 65..71 of C (never written again)
    for (int i = tid; i < 7 * KO; i += 256) {
        Ch[(65 + i / KO) * KO + (i % KO)] = 0;
        Cl[(65 + i / KO) * KO + (i % KO)] = 0;
    }

    float c[9][4];
#pragma unroll
    for (int nt = 0; nt < 9; nt++)
#pragma unroll
        for (int u = 0; u < 4; u++) c[nt][u] = 0.f;

    const int qrow = tid >> 1, qhalf = tid & 1;    // qp staging coords
    const int ce = tid & 63, cg = tid >> 6;        // ctx staging coords

    for (int jc = 0; jc < J; jc += 64) {
        __syncthreads();
        // qp chunk [128][64] -> Qh/Ql
        {
            const float* qb = g_qp + (row0 + qrow) * J + jc + qhalf * 32;
#pragma unroll
            for (int i = 0; i < 16; i++) {
                float2 f = *(const float2*)(qb + 2 * i);
                uint32_t hi, lo;
                split2(f.x, f.y, hi, lo);
                Qh[qrow * KO + qhalf * 16 + i] = hi;
                Ql[qrow * KO + qhalf * 16 + i] = lo;
            }
        }
        // ctx^T chunk: C[e][k=j], e = ce, j = jc + cg*16 .. +15
        {
            const float* cbp = g_ctx + cb + (size_t)(jc + cg * 16) * D + ce;
#pragma unroll
            for (int i = 0; i < 16; i += 2) {
                float f0 = cbp[(size_t)i * D];
                float f1 = cbp[(size_t)(i + 1) * D];
                uint32_t hi, lo;
                split2(f0, f1, hi, lo);
                Ch[ce * KO + cg * 8 + (i >> 1)] = hi;
                Cl[ce * KO + cg * 8 + (i >> 1)] = lo;
            }
        }
        // ksum -> row 64
        if (tid < 32) {
            float f0 = g_ksum[(size_t)bh * J + jc + 2 * tid];
            float f1 = g_ksum[(size_t)bh * J + jc + 2 * tid + 1];
            uint32_t hi, lo;
            split2(f0, f1, hi, lo);
            Ch[64 * KO + tid] = hi;
            Cl[64 * KO + tid] = lo;
        }
        __syncthreads();

#pragma unroll
        for (int ks = 0; ks < 4; ks++) {
            const int kx = ks * 8;
            uint32_t ahi[4], alo[4];
            int m = wid * 16 + qr;
            ahi[0] = Qh[m * KO + kx + qc];
            ahi[1] = Qh[(m + 8) * KO + kx + qc];
            ahi[2] = Qh[m * KO + kx + 4 + qc];
            ahi[3] = Qh[(m + 8) * KO + kx + 4 + qc];
            alo[0] = Ql[m * KO + kx + qc];
            alo[1] = Ql[(m + 8) * KO + kx + qc];
            alo[2] = Ql[m * KO + kx + 4 + qc];
            alo[3] = Ql[(m + 8) * KO + kx + 4 + qc];
#pragma unroll
            for (int nt = 0; nt < 9; nt++) {
                int n = nt * 8 + qr;
                uint32_t bhi[2], blo[2];
                bhi[0] = Ch[n * KO + kx + qc];
                bhi[1] = Ch[n * KO + kx + 4 + qc];
                blo[0] = Cl[n * KO + kx + qc];
                blo[1] = Cl[n * KO + kx + 4 + qc];
                mma16(c[nt], ahi, bhi);
                mma16(c[nt], alo, bhi);
                mma16(c[nt], ahi, blo);
            }
        }
    }

    // denominator: column 64 = (nt 8, qc 0 lanes)
    const int srcl = lane & ~3;
    float den0 = __shfl_sync(0xffffffffu, c[8][0], srcl);
    float den1 = __shfl_sync(0xffffffffu, c[8][2], srcl);
    float di0 = 1.f / den0, di1 = 1.f / den1;

    const int row = wid * 16 + qr;
#pragma unroll
    for (int nt = 0; nt < 8; nt++) {
        int e = nt * 8 + qc * 2;
        *(float2*)&out[(row0 + row) * D + e] =
            make_float2(c[nt][0] * di0, c[nt][1] * di0);
        *(float2*)&out[(row0 + row + 8) * D + e] =
            make_float2(c[nt][2] * di1, c[nt][3] * di1);
    }
}

} // namespace fa

// ===========================================================================
// Launch
// ===========================================================================
extern "C" void kernel_launch(void* const* d_in, const int* in_sizes, int n_in,
                              void* d_out, int out_size)
{
    using namespace fa;
    (void)in_sizes; (void)n_in; (void)out_size;

    const float* q = (const float*)d_in[0];
    const float* k = (const float*)d_in[1];
    const float* v = (const float*)d_in[2];
    const float* P = (const float*)d_in[3];
    float* out = (float*)d_out;

    cudaFuncSetAttribute(k_proj_t<true>,  cudaFuncAttributeMaxDynamicSharedMemorySize, (int)SMEM_PROJ);
    cudaFuncSetAttribute(k_proj_t<false>, cudaFuncAttributeMaxDynamicSharedMemorySize, (int)SMEM_PROJ);
    cudaFuncSetAttribute(k_ctx_t,         cudaFuncAttributeMaxDynamicSharedMemorySize, (int)SMEM_CTX);
    cudaFuncSetAttribute(k_out_t,         cudaFuncAttributeMaxDynamicSharedMemorySize, (int)SMEM_OUT);

    k_prep<<<8, 1024>>>(P);                                     // split P, init max
    k_proj_t<false><<<(int)(NT / 64), 256, SMEM_PROJ>>>(k);     // k logits + max
    k_proj_t<true ><<<(int)(NT / 64), 256, SMEM_PROJ>>>(q);     // qp
    k_ctx_t<<<dim3(BH, SPLIT), 256, SMEM_CTX>>>(v);             // exp + context
    k_red<<<BH, 256>>>();                                       // reduce partials
    k_out_t<<<(int)(NT / 128), 256, SMEM_OUT>>>(out);           // qp@[ctx|ksum]/den
}

// round 4
// speedup vs baseline: 2.4512x; 1.0009x over previous
#include <cuda_runtime.h>
#include <cuda_bf16.h>
#include <math.h>
#include <stdint.h>

// ===========================================================================
// Performer FastAttention — bf16 3-MMA split (m16n8k16), presplit smem.
// Shapes: q,k,v [2,16,4096,64]; projection [256,64]; out [2,16,4096,64].
// ===========================================================================

namespace fa {

constexpr int B  = 2;
constexpr int H  = 16;
constexpr int N  = 4096;
constexpr int D  = 64;
constexpr int J  = 256;
constexpr int BH = B * H;
constexpr size_t NT = (size_t)BH * N;     // 131072 rows
constexpr int SPLIT = 16;

constexpr float DATA_NORM = 0.35355339059327373f;  // 64^-0.25
constexpr float RATIO     = 0.0625f;               // 256^-0.5
constexpr float DIAG_C    = 0.0625f;               // 0.5 * DATA_NORM^2
constexpr float KEPS      = 1e-4f;

// ---- scratch ----
__device__ float    g_qp[NT * J];
__device__ float    g_kp[NT * J];          // logits
__device__ unsigned g_kmax_u;
__device__ float    g_ctxp[(size_t)BH * SPLIT * J * D];
__device__ float    g_ksump[(size_t)BH * SPLIT * J];
__device__ float    g_ctx[(size_t)BH * J * D];
__device__ float    g_ksum[(size_t)BH * J];
__device__ uint32_t g_Ph[J * 32];          // P hi, bf16x2 packed [j][d/2]
__device__ uint32_t g_Pl[J * 32];          // P lo

__device__ __forceinline__ unsigned fenc(float f) {
    unsigned u = __float_as_uint(f);
    return (u & 0x80000000u) ? ~u : (u | 0x80000000u);
}
__device__ __forceinline__ float fdec(unsigned u) {
    unsigned b = (u & 0x80000000u) ? (u & 0x7fffffffu) : ~u;
    return __uint_as_float(b);
}

// pack two floats as bf16x2 (lo half = a, hi half = b), round-to-nearest
__device__ __forceinline__ uint32_t bpack(float a, float b) {
    uint32_t r;
    asm("cvt.rn.bf16x2.f32 %0, %1, %2;" : "=r"(r) : "f"(b), "f"(a));
    return r;
}
// split pair (a,b) into bf16 hi + bf16 lo packed words
__device__ __forceinline__ void split2(float a, float b, uint32_t& hi, uint32_t& lo) {
    hi = bpack(a, b);
    float ha = __uint_as_float(hi << 16);
    float hb = __uint_as_float(hi & 0xffff0000u);
    lo = bpack(a - ha, b - hb);
}

// m16n8k16 bf16 mma, fp32 accumulate
__device__ __forceinline__ void mma16(float* c, const uint32_t* a, const uint32_t* b) {
    asm volatile(
        "mma.sync.aligned.m16n8k16.row.col.f32.bf16.bf16.f32 "
        "{%0,%1,%2,%3}, {%4,%5,%6,%7}, {%8,%9}, {%0,%1,%2,%3};"
        : "+f"(c[0]), "+f"(c[1]), "+f"(c[2]), "+f"(c[3])
        : "r"(a[0]), "r"(a[1]), "r"(a[2]), "r"(a[3]), "r"(b[0]), "r"(b[1]));
}

// ===========================================================================
// Prep: split projection P [256][64] into g_Ph/g_Pl; init global max cell.
// ===========================================================================
__global__ void k_prep(const float* __restrict__ P)
{
    int i = blockIdx.x * blockDim.x + threadIdx.x;   // 8192 pair slots
    if (i == 0) g_kmax_u = 0x007FFFFFu;              // fenc(-inf)
    if (i < J * 32) {
        int j = i >> 5, c = i & 31;
        uint32_t hi, lo;
        split2(P[j * 64 + 2 * c], P[j * 64 + 2 * c + 1], hi, lo);
        g_Ph[i] = hi;
        g_Pl[i] = lo;
    }
}

// ===========================================================================
// Projection: dd = DATA_NORM * (X @ P^T); 64 rows x 256 cols per block.
//   IS_Q: g_qp = RATIO*(exp(dd - diag - rowmax)+eps)
//  !IS_Q: g_kp = dd - diag (logits); atomicMax global max(dd)
// 8 warps as 2(m) x 4(n); warp tile 32x64; K=64 (4 ksteps of 16).
// smem (u32 units): Phs[256][36], Pls[256][36], xhs[64][36], xls[64][36].
// ===========================================================================
constexpr int KP = 36;   // u32 row stride (K=64 -> 32 u32 + 4 pad)
constexpr size_t SMEM_PROJ = (size_t)(2 * J * KP + 2 * 64 * KP) * sizeof(uint32_t);

template <bool IS_Q>
__global__ void __launch_bounds__(256)
k_proj_t(const float* __restrict__ x)
{
    extern __shared__ uint32_t smu[];
    uint32_t* Phs = smu;                  // [256][36]
    uint32_t* Pls = Phs + J * KP;
    uint32_t* xhs = Pls + J * KP;         // [64][36]
    uint32_t* xls = xhs + 64 * KP;
    __shared__ float diag[64];
    __shared__ float red[64][4];

    const int tid = threadIdx.x;
    const size_t row0 = (size_t)blockIdx.x * 64;
    const float* xb = x + row0 * D;

    // stage pre-split P (u32 copies)
    for (int i = tid; i < J * 32; i += 256) {
        int j = i >> 5, c = i & 31;
        Phs[j * KP + c] = g_Ph[i];
        Pls[j * KP + c] = g_Pl[i];
    }
    // stage + split x
    for (int i = tid; i < 64 * 32; i += 256) {
        int r = i >> 5, c = i & 31;
        float2 f = *(const float2*)(xb + r * 64 + 2 * c);
        uint32_t hi, lo;
        split2(f.x, f.y, hi, lo);
        xhs[r * KP + c] = hi;
        xls[r * KP + c] = lo;
    }
    // diag from global (full fp32 precision)
    if (tid < 64) {
        const float4* xr = (const float4*)(xb + tid * 64);
        float s = 0.f;
#pragma unroll
        for (int i = 0; i < 16; i++) {
            float4 f = xr[i];
            s = fmaf(f.x, f.x, s); s = fmaf(f.y, f.y, s);
            s = fmaf(f.z, f.z, s); s = fmaf(f.w, f.w, s);
        }
        diag[tid] = s * DIAG_C;
    }
    __syncthreads();

    const int lane = tid & 31, wid = tid >> 5;
    const int wm = wid >> 2, wn = wid & 3;   // rows wm*32, cols wn*64
    const int qr = lane >> 2, qc = lane & 3;

    float c[2][8][4];
#pragma unroll
    for (int mt = 0; mt < 2; mt++)
#pragma unroll
        for (int nt = 0; nt < 8; nt++)
#pragma unroll
            for (int u = 0; u < 4; u++) c[mt][nt][u] = 0.f;

#pragma unroll
    for (int ks = 0; ks < 4; ks++) {
        const int kx = ks * 8;
        uint32_t ahi[2][4], alo[2][4];
#pragma unroll
        for (int mt = 0; mt < 2; mt++) {
            int m = wm * 32 + mt * 16 + qr;
            ahi[mt][0] = xhs[m * KP + kx + qc];
            ahi[mt][1] = xhs[(m + 8) * KP + kx + qc];
            ahi[mt][2] = xhs[m * KP + kx + 4 + qc];
            ahi[mt][3] = xhs[(m + 8) * KP + kx + 4 + qc];
            alo[mt][0] = xls[m * KP + kx + qc];
            alo[mt][1] = xls[(m + 8) * KP + kx + qc];
            alo[mt][2] = xls[m * KP + kx + 4 + qc];
            alo[mt][3] = xls[(m + 8) * KP + kx + 4 + qc];
        }
#pragma unroll
        for (int nt = 0; nt < 8; nt++) {
            int j = wn * 64 + nt * 8 + qr;
            uint32_t bhi[2], blo[2];
            bhi[0] = Phs[j * KP + kx + qc];
            bhi[1] = Phs[j * KP + kx + 4 + qc];
            blo[0] = Pls[j * KP + kx + qc];
            blo[1] = Pls[j * KP + kx + 4 + qc];
#pragma unroll
            for (int mt = 0; mt < 2; mt++) {
                mma16(c[mt][nt], ahi[mt], bhi);
                mma16(c[mt][nt], alo[mt], bhi);
                mma16(c[mt][nt], ahi[mt], blo);
            }
        }
    }

    const float NEG_INF = __int_as_float(0xff800000);

    if (IS_Q) {
        float rmax[2][2];
#pragma unroll
        for (int mt = 0; mt < 2; mt++) { rmax[mt][0] = NEG_INF; rmax[mt][1] = NEG_INF; }
#pragma unroll
        for (int mt = 0; mt < 2; mt++)
#pragma unroll
            for (int nt = 0; nt < 8; nt++) {
                rmax[mt][0] = fmaxf(rmax[mt][0], fmaxf(c[mt][nt][0], c[mt][nt][1]));
                rmax[mt][1] = fmaxf(rmax[mt][1], fmaxf(c[mt][nt][2], c[mt][nt][3]));
            }
#pragma unroll
        for (int mt = 0; mt < 2; mt++)
#pragma unroll
            for (int h = 0; h < 2; h++) {
                rmax[mt][h] = fmaxf(rmax[mt][h], __shfl_xor_sync(0xffffffffu, rmax[mt][h], 1));
                rmax[mt][h] = fmaxf(rmax[mt][h], __shfl_xor_sync(0xffffffffu, rmax[mt][h], 2));
            }
        if (qc == 0) {
#pragma unroll
            for (int mt = 0; mt < 2; mt++) {
                red[wm * 32 + mt * 16 + qr][wn]     = rmax[mt][0];
                red[wm * 32 + mt * 16 + qr + 8][wn] = rmax[mt][1];
            }
        }
        __syncthreads();
        float sub[2][2];
#pragma unroll
        for (int mt = 0; mt < 2; mt++)
#pragma unroll
            for (int h = 0; h < 2; h++) {
                int row = wm * 32 + mt * 16 + qr + h * 8;
                float m4 = fmaxf(fmaxf(red[row][0], red[row][1]),
                                 fmaxf(red[row][2], red[row][3])) * DATA_NORM;
                sub[mt][h] = diag[row] + m4;
            }
#pragma unroll
        for (int mt = 0; mt < 2; mt++)
#pragma unroll
            for (int nt = 0; nt < 8; nt++) {
                int row = wm * 32 + mt * 16 + qr;
                int j = wn * 64 + nt * 8 + qc * 2;
                float2 v0, v1;
                v0.x = RATIO * (__expf(fmaf(c[mt][nt][0], DATA_NORM, -sub[mt][0])) + KEPS);
                v0.y = RATIO * (__expf(fmaf(c[mt][nt][1], DATA_NORM, -sub[mt][0])) + KEPS);
                v1.x = RATIO * (__expf(fmaf(c[mt][nt][2], DATA_NORM, -sub[mt][1])) + KEPS);
                v1.y = RATIO * (__expf(fmaf(c[mt][nt][3], DATA_NORM, -sub[mt][1])) + KEPS);
                *(float2*)&g_qp[(row0 + row) * J + j]     = v0;
                *(float2*)&g_qp[(row0 + row + 8) * J + j] = v1;
            }
    } else {
        float bm = NEG_INF;
#pragma unroll
        for (int mt = 0; mt < 2; mt++)
#pragma unroll
            for (int nt = 0; nt < 8; nt++)
#pragma unroll
                for (int u = 0; u < 4; u++) bm = fmaxf(bm, c[mt][nt][u]);
#pragma unroll
        for (int o = 16; o > 0; o >>= 1)
            bm = fmaxf(bm, __shfl_xor_sync(0xffffffffu, bm, o));
        if (lane == 0) red[wid][0] = bm;
        __syncthreads();
        if (tid == 0) {
            float m = red[0][0];
#pragma unroll
            for (int w = 1; w < 8; w++) m = fmaxf(m, red[w][0]);
            atomicMax(&g_kmax_u, fenc(m * DATA_NORM));
        }
#pragma unroll
        for (int mt = 0; mt < 2; mt++) {
            int rbase = wm * 32 + mt * 16 + qr;
            float d0 = diag[rbase], d1 = diag[rbase + 8];
#pragma unroll
            for (int nt = 0; nt < 8; nt++) {
                int j = wn * 64 + nt * 8 + qc * 2;
                float2 v0, v1;
                v0.x = fmaf(c[mt][nt][0], DATA_NORM, -d0);
                v0.y = fmaf(c[mt][nt][1], DATA_NORM, -d0);
                v1.x = fmaf(c[mt][nt][2], DATA_NORM, -d1);
                v1.y = fmaf(c[mt][nt][3], DATA_NORM, -d1);
                *(float2*)&g_kp[(row0 + rbase) * J + j]     = v0;
                *(float2*)&g_kp[(row0 + rbase + 8) * J + j] = v1;
            }
        }
    }
}

// ===========================================================================
// Context GEMM (split-K): ctxp[j][e] = sum_n kp[n][j]*v[n][e]; ksump[j].
// exp fused at staging. grid (BH, SPLIT); 256 thr; 8 warps = 4(m) x 2(n).
// smem (u32): Ah/Al [256][20] (A = kp^T, K=n chunk 32), Bh/Bl [64][20].
// ===========================================================================
constexpr int KC = 20;   // u32 stride for K=32 (16 u32 + 4 pad)
constexpr size_t SMEM_CTX = (size_t)(2 * J * KC + 2 * 64 * KC) * sizeof(uint32_t);

__global__ void __launch_bounds__(256)
k_ctx_t(const float* __restrict__ vg)
{
    extern __shared__ uint32_t smu[];
    uint32_t* Ah = smu;                 // [256][20]
    uint32_t* Al = Ah + J * KC;
    uint32_t* Bh = Al + J * KC;         // [64][20]
    uint32_t* Bl = Bh + 64 * KC;

    const int bh = blockIdx.x, s = blockIdx.y;
    const int tid = threadIdx.x, lane = tid & 31, wid = tid >> 5;
    const int wm = wid >> 1, wn = wid & 1;
    const int qr = lane >> 2, qc = lane & 3;
    const float gmax = fdec(g_kmax_u);

    constexpr int NC = N / SPLIT;       // 256
    const size_t base = (size_t)bh * N + (size_t)s * NC;

    float c[4][4][4];
#pragma unroll
    for (int mt = 0; mt < 4; mt++)
#pragma unroll
        for (int nt = 0; nt < 4; nt++)
#pragma unroll
            for (int u = 0; u < 4; u++) c[mt][nt][u] = 0.f;
    float kss = 0.f;

    const int ve = tid & 63, vh = tid >> 6;    // v staging coords

    for (int n0 = 0; n0 < NC; n0 += 32) {
        __syncthreads();
        // kp: thread = column j; apply exp; split into A (j-major, k=n)
        {
            const float* kpc = g_kp + (base + n0) * J + tid;
#pragma unroll
            for (int n = 0; n < 32; n += 2) {
                float v0 = RATIO * (__expf(kpc[(size_t)n * J] - gmax) + KEPS);
                float v1 = RATIO * (__expf(kpc[(size_t)(n + 1) * J] - gmax) + KEPS);
                kss += v0 + v1;
                uint32_t hi, lo;
                split2(v0, v1, hi, lo);
                Ah[tid * KC + (n >> 1)] = hi;
                Al[tid * KC + (n >> 1)] = lo;
            }
        }
        // v: B[e][k=n]
        {
            const float* vb = vg + (base + n0 + vh * 8) * D + ve;
#pragma unroll
            for (int i = 0; i < 8; i += 2) {
                float f0 = vb[(size_t)i * D];
                float f1 = vb[(size_t)(i + 1) * D];
                uint32_t hi, lo;
                split2(f0, f1, hi, lo);
                Bh[ve * KC + vh * 4 + (i >> 1)] = hi;
                Bl[ve * KC + vh * 4 + (i >> 1)] = lo;
            }
        }
        __syncthreads();

#pragma unroll
        for (int ks = 0; ks < 2; ks++) {
            const int kx = ks * 8;
            uint32_t ahi[4][4], alo[4][4];
#pragma unroll
            for (int mt = 0; mt < 4; mt++) {
                int m = wm * 64 + mt * 16 + qr;
                ahi[mt][0] = Ah[m * KC + kx + qc];
                ahi[mt][1] = Ah[(m + 8) * KC + kx + qc];
                ahi[mt][2] = Ah[m * KC + kx + 4 + qc];
                ahi[mt][3] = Ah[(m + 8) * KC + kx + 4 + qc];
                alo[mt][0] = Al[m * KC + kx + qc];
                alo[mt][1] = Al[(m + 8) * KC + kx + qc];
                alo[mt][2] = Al[m * KC + kx + 4 + qc];
                alo[mt][3] = Al[(m + 8) * KC + kx + 4 + qc];
            }
#pragma unroll
            for (int nt = 0; nt < 4; nt++) {
                int e = wn * 32 + nt * 8 + qr;
                uint32_t bhi[2], blo[2];
                bhi[0] = Bh[e * KC + kx + qc];
                bhi[1] = Bh[e * KC + kx + 4 + qc];
                blo[0] = Bl[e * KC + kx + qc];
                blo[1] = Bl[e * KC + kx + 4 + qc];
#pragma unroll
                for (int mt = 0; mt < 4; mt++) {
                    mma16(c[mt][nt], ahi[mt], bhi);
                    mma16(c[mt][nt], alo[mt], bhi);
                    mma16(c[mt][nt], ahi[mt], blo);
                }
            }
        }
    }

    const size_t ob = (size_t)(bh * SPLIT + s);
#pragma unroll
    for (int mt = 0; mt < 4; mt++)
#pragma unroll
        for (int nt = 0; nt < 4; nt++) {
            int jrow = wm * 64 + mt * 16 + qr;
            int e = wn * 32 + nt * 8 + qc * 2;
            *(float2*)&g_ctxp[(ob * J + jrow) * D + e] =
                make_float2(c[mt][nt][0], c[mt][nt][1]);
            *(float2*)&g_ctxp[(ob * J + jrow + 8) * D + e] =
                make_float2(c[mt][nt][2], c[mt][nt][3]);
        }
    g_ksump[ob * J + tid] = kss;
}

// Reduce split partials. grid = BH, 256 threads.
__global__ void k_red()
{
    const int bh = blockIdx.x;
    for (int i = threadIdx.x; i < J * D; i += 256) {
        float sum = 0.f;
#pragma unroll
        for (int t = 0; t < SPLIT; t++)
            sum += g_ctxp[(size_t)(bh * SPLIT + t) * J * D + i];
        g_ctx[(size_t)bh * J * D + i] = sum;
    }
    {
        const int j = threadIdx.x;
        float sum = 0.f;
#pragma unroll
        for (int t = 0; t < SPLIT; t++)
            sum += g_ksump[(size_t)(bh * SPLIT + t) * J + j];
        g_ksum[(size_t)bh * J + j] = sum;
    }
}

// ===========================================================================
// Output GEMM: out[row][e] = (qp[row] @ ctx)[e] / (qp[row] . ksum)
// den folded as B-row e=64 (rows 65..71 zero). Block 128 rows x 72 x K=256
// (chunks of 64). 8 warps, warp tile 16 x 72.
// smem (u32): Qh/Ql [128][36], Ch/Cl [72][36].
// ===========================================================================
constexpr int KO = 36;
constexpr size_t SMEM_OUT = (size_t)(2 * 128 * KO + 2 * 72 * KO) * sizeof(uint32_t);

__global__ void __launch_bounds__(256)
k_out_t(float* __restrict__ out)
{
    extern __shared__ uint32_t smu[];
    uint32_t* Qh = smu;                  // [128][36]
    uint32_t* Ql = Qh + 128 * KO;
    uint32_t* Ch = Ql + 128 * KO;        // [72][36]
    uint32_t* Cl = Ch + 72 * KO;

    const size_t row0 = (size_t)blockIdx.x * 128;
    const int bh = (int)(row0 / N);
    const size_t cb = (size_t)bh * J * D;
    const int tid = threadIdx.x, lane = tid & 31, wid = tid >> 5;
    const int qr = lane >> 2, qc = lane & 3;

    // zero pad rows 65..71 of C (never written again)
    for (int i = tid; i < 7 * KO; i += 256) {
        Ch[(65 + i / KO) * KO + (i % KO)] = 0;
        Cl[(65 + i / KO) * KO + (i % KO)] = 0;
    }

    float c[9][4];
#pragma unroll
    for (int nt = 0; nt < 9; nt++)
#pragma unroll
        for (int u = 0; u < 4; u++) c[nt][u] = 0.f;

    const int qrow = tid >> 1, qhalf = tid & 1;    // qp staging coords
    const int ce = tid & 63, cg = tid >> 6;        // ctx staging coords

    for (int jc = 0; jc < J; jc += 64) {
        __syncthreads();
        // qp chunk [128][64] -> Qh/Ql
        {
            const float* qb = g_qp + (row0 + qrow) * J + jc + qhalf * 32;
#pragma unroll
            for (int i = 0; i < 16; i++) {
                float2 f = *(const float2*)(qb + 2 * i);
                uint32_t hi, lo;
                split2(f.x, f.y, hi, lo);
                Qh[qrow * KO + qhalf * 16 + i] = hi;
                Ql[qrow * KO + qhalf * 16 + i] = lo;
            }
        }
        // ctx^T chunk: C[e][k=j], e = ce, j = jc + cg*16 .. +15
        {
            const float* cbp = g_ctx + cb + (size_t)(jc + cg * 16) * D + ce;
#pragma unroll
            for (int i = 0; i < 16; i += 2) {
                float f0 = cbp[(size_t)i * D];
                float f1 = cbp[(size_t)(i + 1) * D];
                uint32_t hi, lo;
                split2(f0, f1, hi, lo);
                Ch[ce * KO + cg * 8 + (i >> 1)] = hi;
                Cl[ce * KO + cg * 8 + (i >> 1)] = lo;
            }
        }
        // ksum -> row 64
        if (tid < 32) {
            float f0 = g_ksum[(size_t)bh * J + jc + 2 * tid];
            float f1 = g_ksum[(size_t)bh * J + jc + 2 * tid + 1];
            uint32_t hi, lo;
            split2(f0, f1, hi, lo);
            Ch[64 * KO + tid] = hi;
            Cl[64 * KO + tid] = lo;
        }
        __syncthreads();

#pragma unroll
        for (int ks = 0; ks < 4; ks++) {
            const int kx = ks * 8;
            uint32_t ahi[4], alo[4];
            int m = wid * 16 + qr;
            ahi[0] = Qh[m * KO + kx + qc];
            ahi[1] = Qh[(m + 8) * KO + kx + qc];
            ahi[2] = Qh[m * KO + kx + 4 + qc];
            ahi[3] = Qh[(m + 8) * KO + kx + 4 + qc];
            alo[0] = Ql[m * KO + kx + qc];
            alo[1] = Ql[(m + 8) * KO + kx + qc];
            alo[2] = Ql[m * KO + kx + 4 + qc];
            alo[3] = Ql[(m + 8) * KO + kx + 4 + qc];
#pragma unroll
            for (int nt = 0; nt < 9; nt++) {
                int n = nt * 8 + qr;
                uint32_t bhi[2], blo[2];
                bhi[0] = Ch[n * KO + kx + qc];
                bhi[1] = Ch[n * KO + kx + 4 + qc];
                blo[0] = Cl[n * KO + kx + qc];
                blo[1] = Cl[n * KO + kx + 4 + qc];
                mma16(c[nt], ahi, bhi);
                mma16(c[nt], alo, bhi);
                mma16(c[nt], ahi, blo);
            }
        }
    }

    // denominator: column 64 = (nt 8, qc 0 lanes)
    const int srcl = lane & ~3;
    float den0 = __shfl_sync(0xffffffffu, c[8][0], srcl);
    float den1 = __shfl_sync(0xffffffffu, c[8][2], srcl);
    float di0 = 1.f / den0, di1 = 1.f / den1;

    const int row = wid * 16 + qr;
#pragma unroll
    for (int nt = 0; nt < 8; nt++) {
        int e = nt * 8 + qc * 2;
        *(float2*)&out[(row0 + row) * D + e] =
            make_float2(c[nt][0] * di0, c[nt][1] * di0);
        *(float2*)&out[(row0 + row + 8) * D + e] =
            make_float2(c[nt][2] * di1, c[nt][3] * di1);
    }
}

} // namespace fa

// ===========================================================================
// Launch
// ===========================================================================
extern "C" void kernel_launch(void* const* d_in, const int* in_sizes, int n_in,
                              void* d_out, int out_size)
{
    using namespace fa;
    (void)in_sizes; (void)n_in; (void)out_size;

    const float* q = (const float*)d_in[0];
    const float* k = (const float*)d_in[1];
    const float* v = (const float*)d_in[2];
    const float* P = (const float*)d_in[3];
    float* out = (float*)d_out;

    cudaFuncSetAttribute(k_proj_t<true>,  cudaFuncAttributeMaxDynamicSharedMemorySize, (int)SMEM_PROJ);
    cudaFuncSetAttribute(k_proj_t<false>, cudaFuncAttributeMaxDynamicSharedMemorySize, (int)SMEM_PROJ);
    cudaFuncSetAttribute(k_ctx_t,         cudaFuncAttributeMaxDynamicSharedMemorySize, (int)SMEM_CTX);
    cudaFuncSetAttribute(k_out_t,         cudaFuncAttributeMaxDynamicSharedMemorySize, (int)SMEM_OUT);

    k_prep<<<8, 1024>>>(P);                                     // split P, init max
    k_proj_t<false><<<(int)(NT / 64), 256, SMEM_PROJ>>>(k);     // k logits + max
    k_proj_t<true ><<<(int)(NT / 64), 256, SMEM_PROJ>>>(q);     // qp
    k_ctx_t<<<dim3(BH, SPLIT), 256, SMEM_CTX>>>(v);             // exp + context
    k_red<<<BH, 256>>>();                                       // reduce partials
    k_out_t<<<(int)(NT / 128), 256, SMEM_OUT>>>(out);           // qp@[ctx|ksum]/den
}

// round 5
// speedup vs baseline: 2.5280x; 1.0313x over previous
#include <cuda_runtime.h>
#include <cuda_bf16.h>
#include <math.h>
#include <stdint.h>

namespace fa {

constexpr int N4 = 4096, D = 64, J = 256, BH = 32, SPLIT = 16;
constexpr size_t NT = (size_t)BH * N4;          // 131072 rows

constexpr float DATA_NORM = 0.35355339059327373f;
constexpr float RATIO     = 0.0625f;
constexpr float DIAG_C    = 0.0625f;
constexpr float KEPS      = 1e-4f;

// ---- scratch ----
__device__ uint32_t g_Ph[J * 32], g_Pl[J * 32];
__device__ __align__(16) uint32_t g_qp_h[NT * 128];   // qp, fragment-tiled
__device__ __align__(16) uint32_t g_qp_l[NT * 128];
__device__ __align__(16) uint32_t g_ET_h[(size_t)BH * 16 * 256 * 128]; // E^T tiles
__device__ __align__(16) uint32_t g_ET_l[(size_t)BH * 16 * 256 * 128];
__device__ __align__(16) uint32_t g_vt_h[(size_t)BH * 72 * 2048];      // v^T (+ones)
__device__ __align__(16) uint32_t g_vt_l[(size_t)BH * 72 * 2048];
__device__ float    g_vsump[BH * 32 * 64];
__device__ float    g_ctxp[(size_t)BH * SPLIT * 256 * 72];
__device__ __align__(16) uint32_t g_bout_h[BH * 72 * 128];
__device__ __align__(16) uint32_t g_bout_l[BH * 72 * 128];
__device__ unsigned g_kmax_u;

__device__ __forceinline__ unsigned fenc(float f) {
    unsigned u = __float_as_uint(f);
    return (u & 0x80000000u) ? ~u : (u | 0x80000000u);
}
__device__ __forceinline__ float fdec(unsigned u) {
    unsigned b = (u & 0x80000000u) ? (u & 0x7fffffffu) : ~u;
    return __uint_as_float(b);
}
__device__ __forceinline__ uint32_t bpack(float a, float b) {
    uint32_t r;
    asm("cvt.rn.bf16x2.f32 %0, %1, %2;" : "=r"(r) : "f"(b), "f"(a));
    return r;
}
__device__ __forceinline__ void split2(float a, float b, uint32_t& hi, uint32_t& lo) {
    hi = bpack(a, b);
    float ha = __uint_as_float(hi << 16);
    float hb = __uint_as_float(hi & 0xffff0000u);
    lo = bpack(a - ha, b - hb);
}
// fp32 exp via FMA-pipe poly (rel err ~1.7e-7), saturating at fp32 range edges
__device__ __forceinline__ float fexp(float x) {
    float t = x * 1.4426950408889634f;
    float r = rintf(t);
    float f = t - r;
    float p = 1.53989857e-4f;
    p = fmaf(p, f, 1.33335581e-3f);
    p = fmaf(p, f, 9.61812910e-3f);
    p = fmaf(p, f, 5.55041087e-2f);
    p = fmaf(p, f, 2.40226507e-1f);
    p = fmaf(p, f, 6.93147181e-1f);
    p = fmaf(p, f, 1.0f);
    int ei = (int)r;
    ei = ei < -126 ? -126 : (ei > 127 ? 127 : ei);
    return p * __int_as_float((ei + 127) << 23);
}
__device__ __forceinline__ void mma16(float* c, const uint32_t* a, const uint32_t* b) {
    asm volatile(
        "mma.sync.aligned.m16n8k16.row.col.f32.bf16.bf16.f32 "
        "{%0,%1,%2,%3}, {%4,%5,%6,%7}, {%8,%9}, {%0,%1,%2,%3};"
        : "+f"(c[0]), "+f"(c[1]), "+f"(c[2]), "+f"(c[3])
        : "r"(a[0]), "r"(a[1]), "r"(a[2]), "r"(a[3]), "r"(b[0]), "r"(b[1]));
}

// ===========================================================================
// Prep P: split to g_Ph/g_Pl; init max.  <<<1,256>>>
// ===========================================================================
__global__ void k_prep_P(const float* __restrict__ P)
{
    const int j = threadIdx.x;
    if (j == 0) g_kmax_u = 0x007FFFFFu;
#pragma unroll
    for (int c = 0; c < 32; c++) {
        uint32_t hi, lo;
        split2(P[j * 64 + 2 * c], P[j * 64 + 2 * c + 1], hi, lo);
        g_Ph[j * 32 + c] = hi;
        g_Pl[j * 32 + c] = lo;
    }
}

// ===========================================================================
// Prep v: v^T split bf16 [bh][72][2048 words] (row64=ones, 65..71=0) + vsum
// partials.  grid (32 bh, 32 chunks of 128 n), 256 thr.
// ===========================================================================
__global__ void __launch_bounds__(256) k_prep_v(const float* __restrict__ v)
{
    __shared__ float vsm[128 * 65];
    const int bh = blockIdx.x, ch = blockIdx.y, tid = threadIdx.x;
    const size_t base = ((size_t)bh * N4 + (size_t)ch * 128) * D;
    for (int i = tid; i < 128 * 64; i += 256)
        vsm[(i >> 6) * 65 + (i & 63)] = v[base + i];
    __syncthreads();

    if (tid < 64) {
        float s = 0.f;
#pragma unroll 8
        for (int n = 0; n < 128; n++) s += vsm[n * 65 + tid];
        g_vsump[(bh * 32 + ch) * 64 + tid] = s;
    }
    {
        const int e = tid >> 2, q = tid & 3;
        const size_t dst = ((size_t)(bh * 72 + e)) * 2048 + ch * 64 + q * 16;
#pragma unroll
        for (int i = 0; i < 16; i++) {
            int n = q * 32 + 2 * i;
            uint32_t hi, lo;
            split2(vsm[n * 65 + e], vsm[(n + 1) * 65 + e], hi, lo);
            g_vt_h[dst + i] = hi;
            g_vt_l[dst + i] = lo;
        }
    }
    for (int i = tid; i < 8 * 64; i += 256) {
        int e = 64 + (i >> 6), w = i & 63;
        size_t d2 = ((size_t)(bh * 72 + e)) * 2048 + ch * 64 + w;
        g_vt_h[d2] = (e == 64) ? 0x3F803F80u : 0u;   // bf16x2 (1,1) or 0
        g_vt_l[d2] = 0u;
    }
}

// ===========================================================================
// Projection: 64 rows x 256 j per block; bf16 3-split MMA (as R3).
//  IS_Q: qp = RATIO*(fexp(dd-diag-rowmax)+eps), stored fragment-tiled.
// !IS_Q: E = fexp(dd-diag) stored fragment-tiled transposed (E^T); atomicMax.
// ===========================================================================
constexpr int KP = 36;
constexpr size_t SMEM_PROJ = (size_t)(2 * J * KP + 2 * 64 * KP) * sizeof(uint32_t);

template <bool IS_Q>
__global__ void __launch_bounds__(256)
k_proj_t(const float* __restrict__ x)
{
    extern __shared__ uint32_t smu[];
    uint32_t* Phs = smu;                  // [256][36]
    uint32_t* Pls = Phs + J * KP;
    uint32_t* xhs = Pls + J * KP;         // [64][36]
    uint32_t* xls = xhs + 64 * KP;
    __shared__ float diag[64];
    __shared__ float red[64][4];

    const int tid = threadIdx.x;
    const size_t row0 = (size_t)blockIdx.x * 64;
    const float* xb = x + row0 * D;

    for (int i = tid; i < J * 32; i += 256) {
        Phs[(i >> 5) * KP + (i & 31)] = g_Ph[i];
        Pls[(i >> 5) * KP + (i & 31)] = g_Pl[i];
    }
    for (int i = tid; i < 64 * 32; i += 256) {
        int r = i >> 5, c = i & 31;
        float2 f = *(const float2*)(xb + r * 64 + 2 * c);
        uint32_t hi, lo;
        split2(f.x, f.y, hi, lo);
        xhs[r * KP + c] = hi;
        xls[r * KP + c] = lo;
    }
    if (tid < 64) {
        const float4* xr = (const float4*)(xb + tid * 64);
        float s = 0.f;
#pragma unroll
        for (int i = 0; i < 16; i++) {
            float4 f = xr[i];
            s = fmaf(f.x, f.x, s); s = fmaf(f.y, f.y, s);
            s = fmaf(f.z, f.z, s); s = fmaf(f.w, f.w, s);
        }
        diag[tid] = s * DIAG_C;
    }
    __syncthreads();

    const int lane = tid & 31, wid = tid >> 5;
    const int wm = wid >> 2, wn = wid & 3;
    const int qr = lane >> 2, qc = lane & 3;

    float c[2][8][4];
#pragma unroll
    for (int mt = 0; mt < 2; mt++)
#pragma unroll
        for (int nt = 0; nt < 8; nt++)
#pragma unroll
            for (int u = 0; u < 4; u++) c[mt][nt][u] = 0.f;

#pragma unroll
    for (int ks = 0; ks < 4; ks++) {
        const int kx = ks * 8;
        uint32_t ahi[2][4], alo[2][4];
#pragma unroll
        for (int mt = 0; mt < 2; mt++) {
            int m = wm * 32 + mt * 16 + qr;
            ahi[mt][0] = xhs[m * KP + kx + qc];
            ahi[mt][1] = xhs[(m + 8) * KP + kx + qc];
            ahi[mt][2] = xhs[m * KP + kx + 4 + qc];
            ahi[mt][3] = xhs[(m + 8) * KP + kx + 4 + qc];
            alo[mt][0] = xls[m * KP + kx + qc];
            alo[mt][1] = xls[(m + 8) * KP + kx + qc];
            alo[mt][2] = xls[m * KP + kx + 4 + qc];
            alo[mt][3] = xls[(m + 8) * KP + kx + 4 + qc];
        }
#pragma unroll
        for (int nt = 0; nt < 8; nt++) {
            int j = wn * 64 + nt * 8 + qr;
            uint32_t bhi[2], blo[2];
            bhi[0] = Phs[j * KP + kx + qc];
            bhi[1] = Phs[j * KP + kx + 4 + qc];
            blo[0] = Pls[j * KP + kx + qc];
            blo[1] = Pls[j * KP + kx + 4 + qc];
#pragma unroll
            for (int mt = 0; mt < 2; mt++) {
                mma16(c[mt][nt], ahi[mt], bhi);
                mma16(c[mt][nt], alo[mt], bhi);
                mma16(c[mt][nt], ahi[mt], blo);
            }
        }
    }

    const float NEG_INF = __int_as_float(0xff800000);

    if (IS_Q) {
        float rmax[2][2];
#pragma unroll
        for (int mt = 0; mt < 2; mt++) { rmax[mt][0] = NEG_INF; rmax[mt][1] = NEG_INF; }
#pragma unroll
        for (int mt = 0; mt < 2; mt++)
#pragma unroll
            for (int nt = 0; nt < 8; nt++) {
                rmax[mt][0] = fmaxf(rmax[mt][0], fmaxf(c[mt][nt][0], c[mt][nt][1]));
                rmax[mt][1] = fmaxf(rmax[mt][1], fmaxf(c[mt][nt][2], c[mt][nt][3]));
            }
#pragma unroll
        for (int mt = 0; mt < 2; mt++)
#pragma unroll
            for (int h = 0; h < 2; h++) {
                rmax[mt][h] = fmaxf(rmax[mt][h], __shfl_xor_sync(0xffffffffu, rmax[mt][h], 1));
                rmax[mt][h] = fmaxf(rmax[mt][h], __shfl_xor_sync(0xffffffffu, rmax[mt][h], 2));
            }
        if (qc == 0) {
#pragma unroll
            for (int mt = 0; mt < 2; mt++) {
                red[wm * 32 + mt * 16 + qr][wn]     = rmax[mt][0];
                red[wm * 32 + mt * 16 + qr + 8][wn] = rmax[mt][1];
            }
        }
        __syncthreads();
        float sub[2][2];
#pragma unroll
        for (int mt = 0; mt < 2; mt++)
#pragma unroll
            for (int h = 0; h < 2; h++) {
                int row = wm * 32 + mt * 16 + qr + h * 8;
                float m4 = fmaxf(fmaxf(red[row][0], red[row][1]),
                                 fmaxf(red[row][2], red[row][3])) * DATA_NORM;
                sub[mt][h] = diag[row] + m4;
            }
        // fragment-tiled store: tile = (row-tile rt, word-tile wt), float4/lane
#pragma unroll
        for (int mt = 0; mt < 2; mt++) {
            size_t rt = (row0 + wm * 32 + mt * 16) >> 4;
#pragma unroll
            for (int u = 0; u < 4; u++) {
                float e00 = RATIO * (fexp(fmaf(c[mt][2*u][0],   DATA_NORM, -sub[mt][0])) + KEPS);
                float e01 = RATIO * (fexp(fmaf(c[mt][2*u][1],   DATA_NORM, -sub[mt][0])) + KEPS);
                float e10 = RATIO * (fexp(fmaf(c[mt][2*u][2],   DATA_NORM, -sub[mt][1])) + KEPS);
                float e11 = RATIO * (fexp(fmaf(c[mt][2*u][3],   DATA_NORM, -sub[mt][1])) + KEPS);
                float f00 = RATIO * (fexp(fmaf(c[mt][2*u+1][0], DATA_NORM, -sub[mt][0])) + KEPS);
                float f01 = RATIO * (fexp(fmaf(c[mt][2*u+1][1], DATA_NORM, -sub[mt][0])) + KEPS);
                float f10 = RATIO * (fexp(fmaf(c[mt][2*u+1][2], DATA_NORM, -sub[mt][1])) + KEPS);
                float f11 = RATIO * (fexp(fmaf(c[mt][2*u+1][3], DATA_NORM, -sub[mt][1])) + KEPS);
                uint4 hi, lo;
                split2(e00, e01, hi.x, lo.x);   // a0: (row, word qc)
                split2(e10, e11, hi.y, lo.y);   // a1: (row+8, word qc)
                split2(f00, f01, hi.z, lo.z);   // a2: (row, word qc+4)
                split2(f10, f11, hi.w, lo.w);   // a3: (row+8, word qc+4)
                size_t t = (rt * 16 + (wn * 4 + u)) * 32 + lane;
                ((uint4*)g_qp_h)[t] = hi;
                ((uint4*)g_qp_l)[t] = lo;
            }
        }
    } else {
        float bm = NEG_INF;
#pragma unroll
        for (int mt = 0; mt < 2; mt++)
#pragma unroll
            for (int nt = 0; nt < 8; nt++)
#pragma unroll
                for (int u = 0; u < 4; u++) bm = fmaxf(bm, c[mt][nt][u]);
#pragma unroll
        for (int o = 16; o > 0; o >>= 1)
            bm = fmaxf(bm, __shfl_xor_sync(0xffffffffu, bm, o));
        if (lane == 0) red[wid][0] = bm;

        // E = fexp(dd - diag) -> smem transpose (reuse P staging region)
        uint16_t* Eh = (uint16_t*)smu;             // [256 j][68 n] bf16
        uint16_t* El = Eh + J * 68;
        __syncthreads();   // done with Phs/xhs; red[] written
        if (tid == 0) {
            float m = red[0][0];
#pragma unroll
            for (int w = 1; w < 8; w++) m = fmaxf(m, red[w][0]);
            atomicMax(&g_kmax_u, fenc(m * DATA_NORM));
        }
#pragma unroll
        for (int mt = 0; mt < 2; mt++) {
            int r0l = wm * 32 + mt * 16 + qr;
            float d0 = diag[r0l], d1 = diag[r0l + 8];
#pragma unroll
            for (int nt = 0; nt < 8; nt++) {
                int j = wn * 64 + nt * 8 + qc * 2;
                float v00 = fexp(fmaf(c[mt][nt][0], DATA_NORM, -d0));
                float v01 = fexp(fmaf(c[mt][nt][1], DATA_NORM, -d0));
                float v10 = fexp(fmaf(c[mt][nt][2], DATA_NORM, -d1));
                float v11 = fexp(fmaf(c[mt][nt][3], DATA_NORM, -d1));
                __nv_bfloat16 h; float hf;
                h = __float2bfloat16(v00); hf = __bfloat162float(h);
                Eh[j * 68 + r0l] = *(uint16_t*)&h;
                { __nv_bfloat16 l = __float2bfloat16(v00 - hf); El[j * 68 + r0l] = *(uint16_t*)&l; }
                h = __float2bfloat16(v01); hf = __bfloat162float(h);
                Eh[(j + 1) * 68 + r0l] = *(uint16_t*)&h;
                { __nv_bfloat16 l = __float2bfloat16(v01 - hf); El[(j + 1) * 68 + r0l] = *(uint16_t*)&l; }
                h = __float2bfloat16(v10); hf = __bfloat162float(h);
                Eh[j * 68 + r0l + 8] = *(uint16_t*)&h;
                { __nv_bfloat16 l = __float2bfloat16(v10 - hf); El[j * 68 + r0l + 8] = *(uint16_t*)&l; }
                h = __float2bfloat16(v11); hf = __bfloat162float(h);
                Eh[(j + 1) * 68 + r0l + 8] = *(uint16_t*)&h;
                { __nv_bfloat16 l = __float2bfloat16(v11 - hf); El[(j + 1) * 68 + r0l + 8] = *(uint16_t*)&l; }
            }
        }
        __syncthreads();
        // gather fragment tiles: 64 tiles (16 jt x 4 wtl) x 32 lanes
        const int bh = (int)(row0 >> 12);          // row0 / 4096
        const size_t nw0 = (row0 & 4095) >> 1;     // local word base (32 words)
        const uint32_t* Ehu = (const uint32_t*)Eh; // [j][34] u32
        const uint32_t* Elu = (const uint32_t*)El;
#pragma unroll
        for (int it = 0; it < 8; it++) {
            int item = it * 256 + tid;
            int tile = item >> 5, l = item & 31;
            int jt = tile >> 2, wtl = tile & 3;
            int jj = jt * 16 + (l >> 2);
            int w  = wtl * 8 + (l & 3);
            uint4 hi, lo;
            hi.x = Ehu[jj * 34 + w];        lo.x = Elu[jj * 34 + w];
            hi.y = Ehu[(jj + 8) * 34 + w];  lo.y = Elu[(jj + 8) * 34 + w];
            hi.z = Ehu[jj * 34 + w + 4];    lo.z = Elu[jj * 34 + w + 4];
            hi.w = Ehu[(jj + 8) * 34 + w+4];lo.w = Elu[(jj + 8) * 34 + w + 4];
            size_t t = (((size_t)bh * 16 + jt) * 256 + (nw0 >> 3) + wtl) * 32 + l;
            ((uint4*)g_ET_h)[t] = hi;
            ((uint4*)g_ET_l)[t] = lo;
        }
    }
}

// ===========================================================================
// Context GEMM: ctxp[j][e] = sum_n E[n][j]*vt[e][n]  (e=64 -> Esum).
// grid (BH, SPLIT); A direct tiled-LDG, B slab in smem.
// 8 warps: warp = 32 j x 72 e; mt=2, nt=9.
// ===========================================================================
constexpr size_t SMEM_CTX = (size_t)(2 * 72 * 132) * sizeof(uint32_t);

__global__ void __launch_bounds__(256) k_ctx_t()
{
    extern __shared__ uint32_t smu[];
    uint32_t* Bsh = smu;              // [72][132]
    uint32_t* Bsl = Bsh + 72 * 132;

    const int bh = blockIdx.x, s = blockIdx.y;
    const int tid = threadIdx.x, lane = tid & 31, wid = tid >> 5;
    const int qr = lane >> 2, qc = lane & 3;

    for (int i = tid; i < 72 * 32; i += 256) {
        int e = i >> 5, w4 = i & 31;
        size_t src = ((size_t)(bh * 72 + e)) * 2048 + s * 128;
        *(float4*)(Bsh + e * 132 + w4 * 4) = ((const float4*)(g_vt_h + src))[w4];
        *(float4*)(Bsl + e * 132 + w4 * 4) = ((const float4*)(g_vt_l + src))[w4];
    }
    __syncthreads();

    float c[2][9][4];
#pragma unroll
    for (int mt = 0; mt < 2; mt++)
#pragma unroll
        for (int nt = 0; nt < 9; nt++)
#pragma unroll
            for (int u = 0; u < 4; u++) c[mt][nt][u] = 0.f;

    const uint4* Ah4[2];
    const uint4* Al4[2];
#pragma unroll
    for (int mt = 0; mt < 2; mt++) {
        size_t tb = (((size_t)bh * 16 + wid * 2 + mt) * 256 + s * 16) * 32 + lane;
        Ah4[mt] = (const uint4*)g_ET_h + tb;
        Al4[mt] = (const uint4*)g_ET_l + tb;
    }

    uint4 cah[2], cal[2], nah[2], nal[2];
#pragma unroll
    for (int mt = 0; mt < 2; mt++) { cah[mt] = Ah4[mt][0]; cal[mt] = Al4[mt][0]; }

#pragma unroll 4
    for (int ck = 0; ck < 16; ck++) {
        if (ck < 15) {
#pragma unroll
            for (int mt = 0; mt < 2; mt++) {
                nah[mt] = Ah4[mt][(ck + 1) * 32];
                nal[mt] = Al4[mt][(ck + 1) * 32];
            }
        }
        const int k0 = ck * 8;
#pragma unroll
        for (int nt = 0; nt < 9; nt++) {
            int e = nt * 8 + qr;
            uint32_t bhi[2], blo[2];
            bhi[0] = Bsh[e * 132 + k0 + qc];
            bhi[1] = Bsh[e * 132 + k0 + 4 + qc];
            blo[0] = Bsl[e * 132 + k0 + qc];
            blo[1] = Bsl[e * 132 + k0 + 4 + qc];
#pragma unroll
            for (int mt = 0; mt < 2; mt++) {
                mma16(c[mt][nt], (const uint32_t*)&cah[mt], bhi);
                mma16(c[mt][nt], (const uint32_t*)&cal[mt], bhi);
                mma16(c[mt][nt], (const uint32_t*)&cah[mt], blo);
            }
        }
#pragma unroll
        for (int mt = 0; mt < 2; mt++) { cah[mt] = nah[mt]; cal[mt] = nal[mt]; }
    }

    const size_t ob = (size_t)(bh * SPLIT + s) * 256;
#pragma unroll
    for (int mt = 0; mt < 2; mt++) {
        int j = wid * 32 + mt * 16 + qr;
#pragma unroll
        for (int nt = 0; nt < 9; nt++) {
            int e = nt * 8 + qc * 2;
            *(float2*)&g_ctxp[(ob + j) * 72 + e]     = make_float2(c[mt][nt][0], c[mt][nt][1]);
            *(float2*)&g_ctxp[(ob + j + 8) * 72 + e] = make_float2(c[mt][nt][2], c[mt][nt][3]);
        }
    }
}

// ===========================================================================
// Reduce + affine + split + transpose -> bout [bh][72 e][128 jw]. grid=BH.
// ===========================================================================
constexpr size_t SMEM_RED = (size_t)(256 * 73) * sizeof(float);

__global__ void __launch_bounds__(256) k_red()
{
    extern __shared__ float sm[];      // [256 j][73]
    __shared__ float vsum[64];
    const int bh = blockIdx.x, tid = threadIdx.x;

    if (tid < 64) {
        float s = 0.f;
#pragma unroll
        for (int cg = 0; cg < 32; cg++) s += g_vsump[(bh * 32 + cg) * 64 + tid];
        vsum[tid] = s;
    }
    {
        float acc[72];
#pragma unroll
        for (int e = 0; e < 72; e++) acc[e] = 0.f;
        for (int s = 0; s < SPLIT; s++) {
            const float4* p = (const float4*)&g_ctxp[((size_t)(bh * SPLIT + s) * 256 + tid) * 72];
#pragma unroll
            for (int w = 0; w < 18; w++) {
                float4 f = p[w];
                acc[w*4+0] += f.x; acc[w*4+1] += f.y; acc[w*4+2] += f.z; acc[w*4+3] += f.w;
            }
        }
#pragma unroll
        for (int e = 0; e < 72; e++) sm[tid * 73 + e] = acc[e];
    }
    __syncthreads();

    const float m = fdec(g_kmax_u);
    const float em = RATIO * expf(-m);
    const float epsn = RATIO * KEPS;
    const int jw = tid & 127, half = tid >> 7;
#pragma unroll
    for (int eo = 0; eo < 36; eo++) {
        int e = half * 36 + eo;
        float v0 = sm[(2 * jw) * 73 + e], v1 = sm[(2 * jw + 1) * 73 + e];
        float a0, a1;
        if (e < 64)       { a0 = fmaf(em, v0, epsn * vsum[e]); a1 = fmaf(em, v1, epsn * vsum[e]); }
        else if (e == 64) { a0 = fmaf(em, v0, epsn * (float)N4); a1 = fmaf(em, v1, epsn * (float)N4); }
        else              { a0 = 0.f; a1 = 0.f; }
        uint32_t hi, lo;
        split2(a0, a1, hi, lo);
        g_bout_h[(bh * 72 + e) * 128 + jw] = hi;
        g_bout_l[(bh * 72 + e) * 128 + jw] = lo;
    }
}

// ===========================================================================
// Output GEMM: out[row][e] = (qp @ [ctx^T|ksum]) / den.  1024 blocks x 128 rows.
// A = g_qp tiles (direct LDG), B = bout slab in smem. warp = 16 rows x 72.
// ===========================================================================
constexpr size_t SMEM_OUT = (size_t)(2 * 72 * 132) * sizeof(uint32_t);

__global__ void __launch_bounds__(256) k_out_t(float* __restrict__ out)
{
    extern __shared__ uint32_t smu[];
    uint32_t* Bsh = smu;              // [72][132]
    uint32_t* Bsl = Bsh + 72 * 132;

    const size_t row0 = (size_t)blockIdx.x * 128;
    const int bh = (int)(row0 >> 12);
    const int tid = threadIdx.x, lane = tid & 31, wid = tid >> 5;
    const int qr = lane >> 2, qc = lane & 3;

    for (int i = tid; i < 72 * 32; i += 256) {
        int e = i >> 5, w4 = i & 31;
        size_t src = (size_t)(bh * 72 + e) * 128;
        *(float4*)(Bsh + e * 132 + w4 * 4) = ((const float4*)(g_bout_h + src))[w4];
        *(float4*)(Bsl + e * 132 + w4 * 4) = ((const float4*)(g_bout_l + src))[w4];
    }
    __syncthreads();

    float c[9][4];
#pragma unroll
    for (int nt = 0; nt < 9; nt++)
#pragma unroll
        for (int u = 0; u < 4; u++) c[nt][u] = 0.f;

    const size_t rt = (row0 >> 4) + wid;
    const uint4* Ah4 = (const uint4*)g_qp_h + (rt * 16) * 32 + lane;
    const uint4* Al4 = (const uint4*)g_qp_l + (rt * 16) * 32 + lane;

    uint4 cah = Ah4[0], cal = Al4[0], nah, nal;
#pragma unroll 4
    for (int ck = 0; ck < 16; ck++) {
        if (ck < 15) { nah = Ah4[(ck + 1) * 32]; nal = Al4[(ck + 1) * 32]; }
        const int k0 = ck * 8;
#pragma unroll
        for (int nt = 0; nt < 9; nt++) {
            int e = nt * 8 + qr;
            uint32_t bhi[2], blo[2];
            bhi[0] = Bsh[e * 132 + k0 + qc];
            bhi[1] = Bsh[e * 132 + k0 + 4 + qc];
            blo[0] = Bsl[e * 132 + k0 + qc];
            blo[1] = Bsl[e * 132 + k0 + 4 + qc];
            mma16(c[nt], (const uint32_t*)&cah, bhi);
            mma16(c[nt], (const uint32_t*)&cal, bhi);
            mma16(c[nt], (const uint32_t*)&cah, blo);
        }
        cah = nah; cal = nal;
    }

    const int srcl = lane & ~3;
    float den0 = __shfl_sync(0xffffffffu, c[8][0], srcl);
    float den1 = __shfl_sync(0xffffffffu, c[8][2], srcl);
    float di0 = 1.f / den0, di1 = 1.f / den1;

    const int row = wid * 16 + qr;
#pragma unroll
    for (int nt = 0; nt < 8; nt++) {
        int e = nt * 8 + qc * 2;
        *(float2*)&out[(row0 + row) * D + e]     = make_float2(c[nt][0] * di0, c[nt][1] * di0);
        *(float2*)&out[(row0 + row + 8) * D + e] = make_float2(c[nt][2] * di1, c[nt][3] * di1);
    }
}

} // namespace fa

extern "C" void kernel_launch(void* const* d_in, const int* in_sizes, int n_in,
                              void* d_out, int out_size)
{
    using namespace fa;
    (void)in_sizes; (void)n_in; (void)out_size;

    const float* q = (const float*)d_in[0];
    const float* k = (const float*)d_in[1];
    const float* v = (const float*)d_in[2];
    const float* P = (const float*)d_in[3];
    float* out = (float*)d_out;

    cudaFuncSetAttribute(k_proj_t<true>,  cudaFuncAttributeMaxDynamicSharedMemorySize, (int)SMEM_PROJ);
    cudaFuncSetAttribute(k_proj_t<false>, cudaFuncAttributeMaxDynamicSharedMemorySize, (int)SMEM_PROJ);
    cudaFuncSetAttribute(k_ctx_t, cudaFuncAttributeMaxDynamicSharedMemorySize, (int)SMEM_CTX);
    cudaFuncSetAttribute(k_red,   cudaFuncAttributeMaxDynamicSharedMemorySize, (int)SMEM_RED);
    cudaFuncSetAttribute(k_out_t, cudaFuncAttributeMaxDynamicSharedMemorySize, (int)SMEM_OUT);

    k_prep_P<<<1, 256>>>(P);
    k_prep_v<<<dim3(BH, 32), 256>>>(v);
    k_proj_t<false><<<(int)(NT / 64), 256, SMEM_PROJ>>>(k);   // E^T tiles + max
    k_ctx_t<<<dim3(BH, SPLIT), 256, SMEM_CTX>>>();            // E^T @ [v|1]
    k_proj_t<true ><<<(int)(NT / 64), 256, SMEM_PROJ>>>(q);   // qp tiles
    k_red<<<BH, 256, SMEM_RED>>>();                           // affine + bout
    k_out_t<<<(int)(NT / 128), 256, SMEM_OUT>>>(out);         // qp@[ctx|ksum]/den
}

// round 6
// speedup vs baseline: 2.8996x; 1.1470x over previous
#include <cuda_runtime.h>
#include <cuda_bf16.h>
#include <math.h>
#include <stdint.h>

namespace fa {

constexpr int N4 = 4096, D = 64, J = 256, BH = 32, SPLIT = 16;
constexpr size_t NT = (size_t)BH * N4;          // 131072 rows

constexpr float DATA_NORM = 0.35355339059327373f;
constexpr float RATIO     = 0.0625f;
constexpr float DIAG_C    = 0.0625f;
constexpr float KEPS      = 1e-4f;

// ---- scratch ----
__device__ uint32_t g_Ph[J * 32], g_Pl[J * 32];
__device__ __align__(16) uint32_t g_qp_h[NT * 128];   // qp, fragment-tiled
__device__ __align__(16) uint32_t g_qp_l[NT * 128];
__device__ __align__(16) uint32_t g_ET_h[(size_t)BH * 16 * 256 * 128]; // E^T tiles
__device__ __align__(16) uint32_t g_ET_l[(size_t)BH * 16 * 256 * 128];
__device__ __align__(16) uint32_t g_vt_h[(size_t)BH * 72 * 2048];      // v^T (+ones)
__device__ __align__(16) uint32_t g_vt_l[(size_t)BH * 72 * 2048];
__device__ float    g_vsump[BH * 32 * 64];
__device__ float    g_ctxp[(size_t)BH * SPLIT * 256 * 72];
__device__ __align__(16) uint32_t g_bout_h[BH * 72 * 128];
__device__ __align__(16) uint32_t g_bout_l[BH * 72 * 128];
__device__ unsigned g_kmax_u;

__device__ __forceinline__ unsigned fenc(float f) {
    unsigned u = __float_as_uint(f);
    return (u & 0x80000000u) ? ~u : (u | 0x80000000u);
}
__device__ __forceinline__ float fdec(unsigned u) {
    unsigned b = (u & 0x80000000u) ? (u & 0x7fffffffu) : ~u;
    return __uint_as_float(b);
}
__device__ __forceinline__ uint32_t bpack(float a, float b) {
    uint32_t r;
    asm("cvt.rn.bf16x2.f32 %0, %1, %2;" : "=r"(r) : "f"(b), "f"(a));
    return r;
}
__device__ __forceinline__ void split2(float a, float b, uint32_t& hi, uint32_t& lo) {
    hi = bpack(a, b);
    float ha = __uint_as_float(hi << 16);
    float hb = __uint_as_float(hi & 0xffff0000u);
    lo = bpack(a - ha, b - hb);
}
// fp32 exp via FMA-pipe poly (rel err ~1.7e-7)
__device__ __forceinline__ float fexp(float x) {
    float t = x * 1.4426950408889634f;
    float r = rintf(t);
    float f = t - r;
    float p = 1.53989857e-4f;
    p = fmaf(p, f, 1.33335581e-3f);
    p = fmaf(p, f, 9.61812910e-3f);
    p = fmaf(p, f, 5.55041087e-2f);
    p = fmaf(p, f, 2.40226507e-1f);
    p = fmaf(p, f, 6.93147181e-1f);
    p = fmaf(p, f, 1.0f);
    int ei = (int)r;
    ei = ei < -126 ? -126 : (ei > 127 ? 127 : ei);
    return p * __int_as_float((ei + 127) << 23);
}
__device__ __forceinline__ void mma16(float* c, const uint32_t* a, const uint32_t* b) {
    asm volatile(
        "mma.sync.aligned.m16n8k16.row.col.f32.bf16.bf16.f32 "
        "{%0,%1,%2,%3}, {%4,%5,%6,%7}, {%8,%9}, {%0,%1,%2,%3};"
        : "+f"(c[0]), "+f"(c[1]), "+f"(c[2]), "+f"(c[3])
        : "r"(a[0]), "r"(a[1]), "r"(a[2]), "r"(a[3]), "r"(b[0]), "r"(b[1]));
}

// ===========================================================================
// Prep P + init max.  <<<1,256>>>
// ===========================================================================
__global__ void k_prep_P(const float* __restrict__ P)
{
    const int j = threadIdx.x;
    if (j == 0) g_kmax_u = 0x007FFFFFu;
#pragma unroll
    for (int c = 0; c < 32; c++) {
        uint32_t hi, lo;
        split2(P[j * 64 + 2 * c], P[j * 64 + 2 * c + 1], hi, lo);
        g_Ph[j * 32 + c] = hi;
        g_Pl[j * 32 + c] = lo;
    }
}

// ===========================================================================
// Prep v: v^T split bf16 [bh][72][2048 w] (row64=ones, 65..71=0) + vsum
// partials. grid (32 bh, 32 chunks of 128 n), 256 thr. Coalesced stores.
// ===========================================================================
__global__ void __launch_bounds__(256) k_prep_v(const float* __restrict__ v)
{
    __shared__ float vsm[128 * 65];
    const int bh = blockIdx.x, ch = blockIdx.y, tid = threadIdx.x;
    const size_t base = ((size_t)bh * N4 + (size_t)ch * 128) * D;
    for (int i = tid; i < 128 * 64; i += 256)
        vsm[(i >> 6) * 65 + (i & 63)] = v[base + i];
    __syncthreads();

    if (tid < 64) {
        float s = 0.f;
#pragma unroll 8
        for (int n = 0; n < 128; n++) s += vsm[n * 65 + tid];
        g_vsump[(bh * 32 + ch) * 64 + tid] = s;
    }
    // coalesced: consecutive tid -> consecutive words within an e-row
    for (int i = tid; i < 72 * 64; i += 256) {
        int e = i >> 6, w = i & 63;
        uint32_t hi, lo;
        if (e < 64) {
            split2(vsm[(2 * w) * 65 + e], vsm[(2 * w + 1) * 65 + e], hi, lo);
        } else if (e == 64) { hi = 0x3F803F80u; lo = 0u; }
        else                { hi = 0u; lo = 0u; }
        size_t dst = ((size_t)(bh * 72 + e)) * 2048 + ch * 64 + w;
        g_vt_h[dst] = hi;
        g_vt_l[dst] = lo;
    }
}

// ===========================================================================
// Projection: 64 rows x 256 j per block; bf16 3-split MMA.
//  IS_Q: qp fragment-tiled.  !IS_Q: E^T fragment-tiled + atomicMax.
// ===========================================================================
constexpr int KP = 36;
constexpr size_t SMEM_PROJ = (size_t)(2 * J * KP + 2 * 64 * KP) * sizeof(uint32_t);

template <bool IS_Q>
__global__ void __launch_bounds__(256, 2)
k_proj_t(const float* __restrict__ x)
{
    extern __shared__ uint32_t smu[];
    uint32_t* Phs = smu;                  // [256][36]
    uint32_t* Pls = Phs + J * KP;
    uint32_t* xhs = Pls + J * KP;         // [64][36]
    uint32_t* xls = xhs + 64 * KP;
    __shared__ float diag[64];
    __shared__ float red[64][4];

    const int tid = threadIdx.x;
    const size_t row0 = (size_t)blockIdx.x * 64;
    const float* xb = x + row0 * D;

    for (int i = tid; i < J * 32; i += 256) {
        Phs[(i >> 5) * KP + (i & 31)] = g_Ph[i];
        Pls[(i >> 5) * KP + (i & 31)] = g_Pl[i];
    }
    for (int i = tid; i < 64 * 32; i += 256) {
        int r = i >> 5, c = i & 31;
        float2 f = *(const float2*)(xb + r * 64 + 2 * c);
        uint32_t hi, lo;
        split2(f.x, f.y, hi, lo);
        xhs[r * KP + c] = hi;
        xls[r * KP + c] = lo;
    }
    if (tid < 64) {
        const float4* xr = (const float4*)(xb + tid * 64);
        float s = 0.f;
#pragma unroll
        for (int i = 0; i < 16; i++) {
            float4 f = xr[i];
            s = fmaf(f.x, f.x, s); s = fmaf(f.y, f.y, s);
            s = fmaf(f.z, f.z, s); s = fmaf(f.w, f.w, s);
        }
        diag[tid] = s * DIAG_C;
    }
    __syncthreads();

    const int lane = tid & 31, wid = tid >> 5;
    const int wm = wid >> 2, wn = wid & 3;
    const int qr = lane >> 2, qc = lane & 3;

    float c[2][8][4];
#pragma unroll
    for (int mt = 0; mt < 2; mt++)
#pragma unroll
        for (int nt = 0; nt < 8; nt++)
#pragma unroll
            for (int u = 0; u < 4; u++) c[mt][nt][u] = 0.f;

#pragma unroll
    for (int ks = 0; ks < 4; ks++) {
        const int kx = ks * 8;
        uint32_t ahi[2][4], alo[2][4];
#pragma unroll
        for (int mt = 0; mt < 2; mt++) {
            int m = wm * 32 + mt * 16 + qr;
            ahi[mt][0] = xhs[m * KP + kx + qc];
            ahi[mt][1] = xhs[(m + 8) * KP + kx + qc];
            ahi[mt][2] = xhs[m * KP + kx + 4 + qc];
            ahi[mt][3] = xhs[(m + 8) * KP + kx + 4 + qc];
            alo[mt][0] = xls[m * KP + kx + qc];
            alo[mt][1] = xls[(m + 8) * KP + kx + qc];
            alo[mt][2] = xls[m * KP + kx + 4 + qc];
            alo[mt][3] = xls[(m + 8) * KP + kx + 4 + qc];
        }
#pragma unroll
        for (int nt = 0; nt < 8; nt++) {
            int j = wn * 64 + nt * 8 + qr;
            uint32_t bhi[2], blo[2];
            bhi[0] = Phs[j * KP + kx + qc];
            bhi[1] = Phs[j * KP + kx + 4 + qc];
            blo[0] = Pls[j * KP + kx + qc];
            blo[1] = Pls[j * KP + kx + 4 + qc];
#pragma unroll
            for (int mt = 0; mt < 2; mt++) {
                mma16(c[mt][nt], ahi[mt], bhi);
                mma16(c[mt][nt], alo[mt], bhi);
                mma16(c[mt][nt], ahi[mt], blo);
            }
        }
    }

    const float NEG_INF = __int_as_float(0xff800000);

    if (IS_Q) {
        float rmax[2][2];
#pragma unroll
        for (int mt = 0; mt < 2; mt++) { rmax[mt][0] = NEG_INF; rmax[mt][1] = NEG_INF; }
#pragma unroll
        for (int mt = 0; mt < 2; mt++)
#pragma unroll
            for (int nt = 0; nt < 8; nt++) {
                rmax[mt][0] = fmaxf(rmax[mt][0], fmaxf(c[mt][nt][0], c[mt][nt][1]));
                rmax[mt][1] = fmaxf(rmax[mt][1], fmaxf(c[mt][nt][2], c[mt][nt][3]));
            }
#pragma unroll
        for (int mt = 0; mt < 2; mt++)
#pragma unroll
            for (int h = 0; h < 2; h++) {
                rmax[mt][h] = fmaxf(rmax[mt][h], __shfl_xor_sync(0xffffffffu, rmax[mt][h], 1));
                rmax[mt][h] = fmaxf(rmax[mt][h], __shfl_xor_sync(0xffffffffu, rmax[mt][h], 2));
            }
        if (qc == 0) {
#pragma unroll
            for (int mt = 0; mt < 2; mt++) {
                red[wm * 32 + mt * 16 + qr][wn]     = rmax[mt][0];
                red[wm * 32 + mt * 16 + qr + 8][wn] = rmax[mt][1];
            }
        }
        __syncthreads();
        float sub[2][2];
#pragma unroll
        for (int mt = 0; mt < 2; mt++)
#pragma unroll
            for (int h = 0; h < 2; h++) {
                int row = wm * 32 + mt * 16 + qr + h * 8;
                float m4 = fmaxf(fmaxf(red[row][0], red[row][1]),
                                 fmaxf(red[row][2], red[row][3])) * DATA_NORM;
                sub[mt][h] = diag[row] + m4;
            }
#pragma unroll
        for (int mt = 0; mt < 2; mt++) {
            size_t rt = (row0 + wm * 32 + mt * 16) >> 4;
#pragma unroll
            for (int u = 0; u < 4; u++) {
                float e00 = RATIO * (fexp(fmaf(c[mt][2*u][0],   DATA_NORM, -sub[mt][0])) + KEPS);
                float e01 = RATIO * (fexp(fmaf(c[mt][2*u][1],   DATA_NORM, -sub[mt][0])) + KEPS);
                float e10 = RATIO * (fexp(fmaf(c[mt][2*u][2],   DATA_NORM, -sub[mt][1])) + KEPS);
                float e11 = RATIO * (fexp(fmaf(c[mt][2*u][3],   DATA_NORM, -sub[mt][1])) + KEPS);
                float f00 = RATIO * (fexp(fmaf(c[mt][2*u+1][0], DATA_NORM, -sub[mt][0])) + KEPS);
                float f01 = RATIO * (fexp(fmaf(c[mt][2*u+1][1], DATA_NORM, -sub[mt][0])) + KEPS);
                float f10 = RATIO * (fexp(fmaf(c[mt][2*u+1][2], DATA_NORM, -sub[mt][1])) + KEPS);
                float f11 = RATIO * (fexp(fmaf(c[mt][2*u+1][3], DATA_NORM, -sub[mt][1])) + KEPS);
                uint4 hi, lo;
                split2(e00, e01, hi.x, lo.x);
                split2(e10, e11, hi.y, lo.y);
                split2(f00, f01, hi.z, lo.z);
                split2(f10, f11, hi.w, lo.w);
                size_t t = (rt * 16 + (wn * 4 + u)) * 32 + lane;
                ((uint4*)g_qp_h)[t] = hi;
                ((uint4*)g_qp_l)[t] = lo;
            }
        }
    } else {
        float bm = NEG_INF;
#pragma unroll
        for (int mt = 0; mt < 2; mt++)
#pragma unroll
            for (int nt = 0; nt < 8; nt++)
#pragma unroll
                for (int u = 0; u < 4; u++) bm = fmaxf(bm, c[mt][nt][u]);
#pragma unroll
        for (int o = 16; o > 0; o >>= 1)
            bm = fmaxf(bm, __shfl_xor_sync(0xffffffffu, bm, o));
        if (lane == 0) red[wid][0] = bm;

        uint16_t* Eh = (uint16_t*)smu;             // [256 j][68 n] bf16
        uint16_t* El = Eh + J * 68;
        __syncthreads();
        if (tid == 0) {
            float m = red[0][0];
#pragma unroll
            for (int w = 1; w < 8; w++) m = fmaxf(m, red[w][0]);
            atomicMax(&g_kmax_u, fenc(m * DATA_NORM));
        }
#pragma unroll
        for (int mt = 0; mt < 2; mt++) {
            int r0l = wm * 32 + mt * 16 + qr;
            float d0 = diag[r0l], d1 = diag[r0l + 8];
#pragma unroll
            for (int nt = 0; nt < 8; nt++) {
                int j = wn * 64 + nt * 8 + qc * 2;
                float v00 = fexp(fmaf(c[mt][nt][0], DATA_NORM, -d0));
                float v01 = fexp(fmaf(c[mt][nt][1], DATA_NORM, -d0));
                float v10 = fexp(fmaf(c[mt][nt][2], DATA_NORM, -d1));
                float v11 = fexp(fmaf(c[mt][nt][3], DATA_NORM, -d1));
                __nv_bfloat16 h; float hf;
                h = __float2bfloat16(v00); hf = __bfloat162float(h);
                Eh[j * 68 + r0l] = *(uint16_t*)&h;
                { __nv_bfloat16 l = __float2bfloat16(v00 - hf); El[j * 68 + r0l] = *(uint16_t*)&l; }
                h = __float2bfloat16(v01); hf = __bfloat162float(h);
                Eh[(j + 1) * 68 + r0l] = *(uint16_t*)&h;
                { __nv_bfloat16 l = __float2bfloat16(v01 - hf); El[(j + 1) * 68 + r0l] = *(uint16_t*)&l; }
                h = __float2bfloat16(v10); hf = __bfloat162float(h);
                Eh[j * 68 + r0l + 8] = *(uint16_t*)&h;
                { __nv_bfloat16 l = __float2bfloat16(v10 - hf); El[j * 68 + r0l + 8] = *(uint16_t*)&l; }
                h = __float2bfloat16(v11); hf = __bfloat162float(h);
                Eh[(j + 1) * 68 + r0l + 8] = *(uint16_t*)&h;
                { __nv_bfloat16 l = __float2bfloat16(v11 - hf); El[(j + 1) * 68 + r0l + 8] = *(uint16_t*)&l; }
            }
        }
        __syncthreads();
        const int bh = (int)(row0 >> 12);
        const size_t nw0 = (row0 & 4095) >> 1;
        const uint32_t* Ehu = (const uint32_t*)Eh;
        const uint32_t* Elu = (const uint32_t*)El;
#pragma unroll
        for (int it = 0; it < 8; it++) {
            int item = it * 256 + tid;
            int tile = item >> 5, l = item & 31;
            int jt = tile >> 2, wtl = tile & 3;
            int jj = jt * 16 + (l >> 2);
            int w  = wtl * 8 + (l & 3);
            uint4 hi, lo;
            hi.x = Ehu[jj * 34 + w];        lo.x = Elu[jj * 34 + w];
            hi.y = Ehu[(jj + 8) * 34 + w];  lo.y = Elu[(jj + 8) * 34 + w];
            hi.z = Ehu[jj * 34 + w + 4];    lo.z = Elu[jj * 34 + w + 4];
            hi.w = Ehu[(jj + 8) * 34 + w+4];lo.w = Elu[(jj + 8) * 34 + w + 4];
            size_t t = (((size_t)bh * 16 + jt) * 256 + (nw0 >> 3) + wtl) * 32 + l;
            ((uint4*)g_ET_h)[t] = hi;
            ((uint4*)g_ET_l)[t] = lo;
        }
    }
}

// ===========================================================================
// Context GEMM: ctxp[j][e] = sum_n E[n][j]*vt[e][n]  (e=64 -> Esum).
// grid (BH, SPLIT); A direct tiled-LDG, B slab in smem.
// ===========================================================================
constexpr size_t SMEM_CTX = (size_t)(2 * 72 * 132) * sizeof(uint32_t);

__global__ void __launch_bounds__(256, 2) k_ctx_t()
{
    extern __shared__ uint32_t smu[];
    uint32_t* Bsh = smu;              // [72][132]
    uint32_t* Bsl = Bsh + 72 * 132;

    const int bh = blockIdx.x, s = blockIdx.y;
    const int tid = threadIdx.x, lane = tid & 31, wid = tid >> 5;
    const int qr = lane >> 2, qc = lane & 3;

    for (int i = tid; i < 72 * 32; i += 256) {
        int e = i >> 5, w4 = i & 31;
        size_t src = ((size_t)(bh * 72 + e)) * 2048 + s * 128;
        *(float4*)(Bsh + e * 132 + w4 * 4) = ((const float4*)(g_vt_h + src))[w4];
        *(float4*)(Bsl + e * 132 + w4 * 4) = ((const float4*)(g_vt_l + src))[w4];
    }
    __syncthreads();

    float c[2][9][4];
#pragma unroll
    for (int mt = 0; mt < 2; mt++)
#pragma unroll
        for (int nt = 0; nt < 9; nt++)
#pragma unroll
            for (int u = 0; u < 4; u++) c[mt][nt][u] = 0.f;

    const uint4* Ah4[2];
    const uint4* Al4[2];
#pragma unroll
    for (int mt = 0; mt < 2; mt++) {
        size_t tb = (((size_t)bh * 16 + wid * 2 + mt) * 256 + s * 16) * 32 + lane;
        Ah4[mt] = (const uint4*)g_ET_h + tb;
        Al4[mt] = (const uint4*)g_ET_l + tb;
    }

    uint4 cah[2], cal[2], nah[2], nal[2];
#pragma unroll
    for (int mt = 0; mt < 2; mt++) { cah[mt] = Ah4[mt][0]; cal[mt] = Al4[mt][0]; }

#pragma unroll 4
    for (int ck = 0; ck < 16; ck++) {
        if (ck < 15) {
#pragma unroll
            for (int mt = 0; mt < 2; mt++) {
                nah[mt] = Ah4[mt][(ck + 1) * 32];
                nal[mt] = Al4[mt][(ck + 1) * 32];
            }
        }
        const int k0 = ck * 8;
#pragma unroll
        for (int nt = 0; nt < 9; nt++) {
            int e = nt * 8 + qr;
            uint32_t bhi[2], blo[2];
            bhi[0] = Bsh[e * 132 + k0 + qc];
            bhi[1] = Bsh[e * 132 + k0 + 4 + qc];
            blo[0] = Bsl[e * 132 + k0 + qc];
            blo[1] = Bsl[e * 132 + k0 + 4 + qc];
#pragma unroll
            for (int mt = 0; mt < 2; mt++) {
                mma16(c[mt][nt], (const uint32_t*)&cah[mt], bhi);
                mma16(c[mt][nt], (const uint32_t*)&cal[mt], bhi);
                mma16(c[mt][nt], (const uint32_t*)&cah[mt], blo);
            }
        }
#pragma unroll
        for (int mt = 0; mt < 2; mt++) { cah[mt] = nah[mt]; cal[mt] = nal[mt]; }
    }

    const size_t ob = (size_t)(bh * SPLIT + s) * 256;
#pragma unroll
    for (int mt = 0; mt < 2; mt++) {
        int j = wid * 32 + mt * 16 + qr;
#pragma unroll
        for (int nt = 0; nt < 9; nt++) {
            int e = nt * 8 + qc * 2;
            *(float2*)&g_ctxp[(ob + j) * 72 + e]     = make_float2(c[mt][nt][0], c[mt][nt][1]);
            *(float2*)&g_ctxp[(ob + j + 8) * 72 + e] = make_float2(c[mt][nt][2], c[mt][nt][3]);
        }
    }
}

// ===========================================================================
// Reduce + affine + split + transpose -> bout.  grid (BH, 8): 32 j rows/block.
// ===========================================================================
__global__ void __launch_bounds__(256) k_red()
{
    __shared__ float sm[32 * 73];
    __shared__ float vsum[64];
    const int bh = blockIdx.x, g = blockIdx.y, tid = threadIdx.x;

    if (tid < 64) {
        float s = 0.f;
#pragma unroll
        for (int cg = 0; cg < 32; cg++) s += g_vsump[(bh * 32 + cg) * 64 + tid];
        vsum[tid] = s;
    }
    {
        const int jl = tid >> 3, eg = tid & 7;    // 32 rows x 8 groups of 9
        float acc[9];
#pragma unroll
        for (int u = 0; u < 9; u++) acc[u] = 0.f;
        for (int s = 0; s < SPLIT; s++) {
            const float* p = &g_ctxp[((size_t)(bh * SPLIT + s) * 256 + g * 32 + jl) * 72 + eg * 9];
#pragma unroll
            for (int u = 0; u < 9; u++) acc[u] += p[u];
        }
#pragma unroll
        for (int u = 0; u < 9; u++) sm[jl * 73 + eg * 9 + u] = acc[u];
    }
    __syncthreads();

    const float m = fdec(g_kmax_u);
    const float em = RATIO * expf(-m);
    const float epsn = RATIO * KEPS;
    // 72 e x 16 jw pairs = 1152 items
    for (int i = tid; i < 72 * 16; i += 256) {
        int e = i >> 4, jwl = i & 15;
        float v0 = sm[(2 * jwl) * 73 + e], v1 = sm[(2 * jwl + 1) * 73 + e];
        float a0, a1;
        if (e < 64)       { a0 = fmaf(em, v0, epsn * vsum[e]); a1 = fmaf(em, v1, epsn * vsum[e]); }
        else if (e == 64) { a0 = fmaf(em, v0, epsn * (float)N4); a1 = fmaf(em, v1, epsn * (float)N4); }
        else              { a0 = 0.f; a1 = 0.f; }
        uint32_t hi, lo;
        split2(a0, a1, hi, lo);
        g_bout_h[(bh * 72 + e) * 128 + g * 16 + jwl] = hi;
        g_bout_l[(bh * 72 + e) * 128 + g * 16 + jwl] = lo;
    }
}

// ===========================================================================
// Output GEMM: out = (qp @ [ctx^T|ksum]) / den.  1024 blocks x 128 rows.
// ===========================================================================
constexpr size_t SMEM_OUT = (size_t)(2 * 72 * 132) * sizeof(uint32_t);

__global__ void __launch_bounds__(256, 2) k_out_t(float* __restrict__ out)
{
    extern __shared__ uint32_t smu[];
    uint32_t* Bsh = smu;              // [72][132]
    uint32_t* Bsl = Bsh + 72 * 132;

    const size_t row0 = (size_t)blockIdx.x * 128;
    const int bh = (int)(row0 >> 12);
    const int tid = threadIdx.x, lane = tid & 31, wid = tid >> 5;
    const int qr = lane >> 2, qc = lane & 3;

    for (int i = tid; i < 72 * 32; i += 256) {
        int e = i >> 5, w4 = i & 31;
        size_t src = (size_t)(bh * 72 + e) * 128;
        *(float4*)(Bsh + e * 132 + w4 * 4) = ((const float4*)(g_bout_h + src))[w4];
        *(float4*)(Bsl + e * 132 + w4 * 4) = ((const float4*)(g_bout_l + src))[w4];
    }
    __syncthreads();

    float c[9][4];
#pragma unroll
    for (int nt = 0; nt < 9; nt++)
#pragma unroll
        for (int u = 0; u < 4; u++) c[nt][u] = 0.f;

    const size_t rt = (row0 >> 4) + wid;
    const uint4* Ah4 = (const uint4*)g_qp_h + (rt * 16) * 32 + lane;
    const uint4* Al4 = (const uint4*)g_qp_l + (rt * 16) * 32 + lane;

    uint4 cah = Ah4[0], cal = Al4[0], nah, nal;
#pragma unroll 4
    for (int ck = 0; ck < 16; ck++) {
        if (ck < 15) { nah = Ah4[(ck + 1) * 32]; nal = Al4[(ck + 1) * 32]; }
        const int k0 = ck * 8;
#pragma unroll
        for (int nt = 0; nt < 9; nt++) {
            int e = nt * 8 + qr;
            uint32_t bhi[2], blo[2];
            bhi[0] = Bsh[e * 132 + k0 + qc];
            bhi[1] = Bsh[e * 132 + k0 + 4 + qc];
            blo[0] = Bsl[e * 132 + k0 + qc];
            blo[1] = Bsl[e * 132 + k0 + 4 + qc];
            mma16(c[nt], (const uint32_t*)&cah, bhi);
            mma16(c[nt], (const uint32_t*)&cal, bhi);
            mma16(c[nt], (const uint32_t*)&cah, blo);
        }
        cah = nah; cal = nal;
    }

    const int srcl = lane & ~3;
    float den0 = __shfl_sync(0xffffffffu, c[8][0], srcl);
    float den1 = __shfl_sync(0xffffffffu, c[8][2], srcl);
    float di0 = 1.f / den0, di1 = 1.f / den1;

    const int row = wid * 16 + qr;
#pragma unroll
    for (int nt = 0; nt < 8; nt++) {
        int e = nt * 8 + qc * 2;
        *(float2*)&out[(row0 + row) * D + e]     = make_float2(c[nt][0] * di0, c[nt][1] * di0);
        *(float2*)&out[(row0 + row + 8) * D + e] = make_float2(c[nt][2] * di1, c[nt][3] * di1);
    }
}

} // namespace fa

extern "C" void kernel_launch(void* const* d_in, const int* in_sizes, int n_in,
                              void* d_out, int out_size)
{
    using namespace fa;
    (void)in_sizes; (void)n_in; (void)out_size;

    const float* q = (const float*)d_in[0];
    const float* k = (const float*)d_in[1];
    const float* v = (const float*)d_in[2];
    const float* P = (const float*)d_in[3];
    float* out = (float*)d_out;

    cudaFuncSetAttribute(k_proj_t<true>,  cudaFuncAttributeMaxDynamicSharedMemorySize, (int)SMEM_PROJ);
    cudaFuncSetAttribute(k_proj_t<false>, cudaFuncAttributeMaxDynamicSharedMemorySize, (int)SMEM_PROJ);
    cudaFuncSetAttribute(k_ctx_t, cudaFuncAttributeMaxDynamicSharedMemorySize, (int)SMEM_CTX);
    cudaFuncSetAttribute(k_out_t, cudaFuncAttributeMaxDynamicSharedMemorySize, (int)SMEM_OUT);

    k_prep_P<<<1, 256>>>(P);
    k_prep_v<<<dim3(BH, 32), 256>>>(v);
    k_proj_t<false><<<(int)(NT / 64), 256, SMEM_PROJ>>>(k);   // E^T tiles + max
    k_ctx_t<<<dim3(BH, SPLIT), 256, SMEM_CTX>>>();            // E^T @ [v|1]
    k_proj_t<true ><<<(int)(NT / 64), 256, SMEM_PROJ>>>(q);   // qp tiles
    k_red<<<dim3(BH, 8), 256>>>();                            // affine + bout
    k_out_t<<<(int)(NT / 128), 256, SMEM_OUT>>>(out);         // qp@[ctx|ksum]/den
}